// round 3
// baseline (speedup 1.0000x reference)
#include <cuda_runtime.h>
#include <cuda_bf16.h>
#include <math.h>
#include <stdint.h>

// ---------------------------------------------------------------------------
// ImageCaptionModel: 2-layer GRU decoder, teacher forced.
//   B=128, T=25, V=10000, E=512, NF=2048, H=512, MAP=512
// All GEMMs on tensor cores via bf16-split 3-pass mma.sync.m16n8k16
// (A = Ahi + Alo in bf16; C += AhiBhi + AhiBlo + AloBhi; fp32 accumulate)
// -> rel error ~1e-5 (effectively fp32), tensor-core speed.
//   1) p = leaky_relu(cnn @ Win + bin)                     (rec_gemm mode 3)
//   2) X[t*B+b] = [emb[tok[b,t]], p[b]]                    (gather)
//   3) A0u/A0r/A0c = X @ (x-rows of W*0) + bias            (big_gemm x3)
//   4) loop over T: recurrent small GEMMs, 8-warp split-K  (rec_gemm x4/step)
//   5) logits = H1all @ Wout + bout  [3200,512]@[512,10000] (big_gemm, remap)
// ---------------------------------------------------------------------------

namespace {
constexpr int cB = 128, cT = 25, cV = 10000, cE = 512, cNF = 2048;
constexpr int cH = 512, cMAP = 512, cIN0 = 1024, cTB = cB * cT;
constexpr long long LOGITS_ELEMS = (long long)cB * cT * cV;  // 32,000,000
}

// Scratch (static __device__ arrays: no allocation allowed)
__device__ float d_P[cB * cMAP];
__device__ float d_X[cTB * cIN0];
__device__ float d_A0u[cTB * cH];
__device__ float d_A0r[cTB * cH];
__device__ float d_A0c[cTB * cH];
__device__ float d_H1[cTB * cH];
__device__ float d_h0[cB * cH];
__device__ float d_h1[cB * cH];
__device__ float d_U0[cB * cH];
__device__ float d_RH0[cB * cH];
__device__ float d_U1[cB * cH];
__device__ float d_RH1[cB * cH];
__device__ int d_tok64;

// ---------------------------------------------------------------------------
// helpers
// ---------------------------------------------------------------------------
__device__ __forceinline__ float sigf(float x) { return 1.0f / (1.0f + __expf(-x)); }

// pack (a,b) -> bf16x2 hi part + bf16x2 residual (lo) part. a in lower 16 bits.
__device__ __forceinline__ void bf16_split(float a, float b, uint32_t& hi, uint32_t& lo) {
    __nv_bfloat162 h;
    h.x = __float2bfloat16_rn(a);
    h.y = __float2bfloat16_rn(b);
    __nv_bfloat162 l;
    l.x = __float2bfloat16_rn(a - __bfloat162float(h.x));
    l.y = __float2bfloat16_rn(b - __bfloat162float(h.y));
    hi = *reinterpret_cast<uint32_t*>(&h);
    lo = *reinterpret_cast<uint32_t*>(&l);
}

__device__ __forceinline__ void mma_bf(
    float& c0, float& c1, float& c2, float& c3,
    uint32_t a0, uint32_t a1, uint32_t a2, uint32_t a3,
    uint32_t b0, uint32_t b1)
{
    asm volatile(
        "mma.sync.aligned.m16n8k16.row.col.f32.bf16.bf16.f32 "
        "{%0,%1,%2,%3}, {%4,%5,%6,%7}, {%8,%9}, {%0,%1,%2,%3};\n"
        : "+f"(c0), "+f"(c1), "+f"(c2), "+f"(c3)
        : "r"(a0), "r"(a1), "r"(a2), "r"(a3), "r"(b0), "r"(b1));
}

// ---------------------------------------------------------------------------
// Token dtype detection (int64 vs int32 ambiguity; see round-0 notes).
// ---------------------------------------------------------------------------
__global__ void detect_tok_kernel(const long long* __restrict__ t) {
    __shared__ int bad;
    if (threadIdx.x == 0) bad = 0;
    __syncthreads();
    for (int i = threadIdx.x; i < cTB / 2; i += blockDim.x) {
        long long v = t[i];
        if (v < 0 || v >= (long long)cV) bad = 1;
    }
    __syncthreads();
    if (threadIdx.x == 0) d_tok64 = (bad == 0) ? 1 : 0;
}

__global__ void init_h_kernel() {
    int i = blockIdx.x * blockDim.x + threadIdx.x;
    if (i < cB * cH) { d_h0[i] = 0.f; d_h1[i] = 0.f; }
}

// X[t*B+b][k] = k<E ? emb[tok[b,t]][k] : P[b][k-E]
__global__ void gather_x_kernel(const long long* __restrict__ tok64,
                                const int* __restrict__ tok32,
                                const float* __restrict__ emb) {
    int i4 = blockIdx.x * blockDim.x + threadIdx.x;
    if (i4 >= cTB * cIN0 / 4) return;
    int idx = i4 * 4;
    int m = idx / cIN0;
    int k = idx % cIN0;
    int tt = m / cB, b = m % cB;
    int tok = d_tok64 ? (int)tok64[b * cT + tt] : tok32[b * cT + tt];
    float4 v;
    if (k < cE) v = *(const float4*)(emb + (long long)tok * cE + k);
    else        v = *(const float4*)(d_P + b * cMAP + (k - cE));
    *(float4*)(d_X + idx) = v;
}

// ---------------------------------------------------------------------------
// Recurrent-loop GEMM (bf16-split tensor cores, 8-warp split-K).
// C = epilogue( A_eff @ W + add + bias ), A_eff = [A0 | A1] (512-col segments)
// M=128, N=512 fixed; K in {512, 1024, 2048}; W row-stride = 512.
// Block: 32x32 output tile, 256 thr = 8 warps, warp k-slice = K/8.
// Per-warp private smem staging (no block syncs in mainloop), smem reduce.
// modes: 0 sigmoid; 1 sigmoid*mul; 2 blend u*mul+(1-u)*tanh (+out2); 3 leaky.
// ---------------------------------------------------------------------------
struct RArgs {
    const float* A0; const float* A1; const float* W;
    const float* add; const float* bias;
    const float* mul; const float* u;
    float* out; float* out2;
    int K; int lda; int mode;
};

__global__ __launch_bounds__(256) void rec_gemm_kernel(RArgs ga, RArgs gb) {
    const RArgs g = (blockIdx.z == 0) ? ga : gb;
    // per-warp staging: Ah/Al 32x9, Wh/Wl 32x9 (u32 each) = 1152 u32/warp.
    // After the K loop (and a __syncthreads) the pool is reused as the
    // 8 x 1024 f32 reduction buffer.
    __shared__ __align__(16) uint32_t pool[8 * 1152];   // 36 KB
    const int tid = threadIdx.x;
    const int wid = tid >> 5, lane = tid & 31;
    const int grp = lane >> 2, tig = lane & 3;
    const int m0 = blockIdx.x * 32, n0 = blockIdx.y * 32;

    uint32_t* Ah = pool + wid * 1152;
    uint32_t* Al = Ah + 288;
    uint32_t* Wh = Ah + 576;
    uint32_t* Wl = Ah + 864;

    const int kslice = g.K >> 3;      // 64 / 128 / 256, multiple of 16
    const int ks0 = wid * kslice;
    const int kp8 = lane & 7;         // W staging: kpair 0..7
    const int ch  = lane >> 3;        // W staging: col-octet 0..3

    float acc[2][4][4] = {};

    for (int it = 0; it < kslice; it += 16) {
        const int kk = ks0 + it;
        // ---- stage A tile 32 x 16 (lane = local row) ----
        {
            const float* ap = (g.A1 && kk >= 512)
                ? (g.A1 + (m0 + lane) * 512 + (kk - 512))
                : (g.A0 + (m0 + lane) * g.lda + kk);
            const float4* ap4 = (const float4*)ap;
            uint32_t* ah = Ah + lane * 9;
            uint32_t* al = Al + lane * 9;
#pragma unroll
            for (int q = 0; q < 4; q++) {
                float4 f = ap4[q];
                uint32_t h, l;
                bf16_split(f.x, f.y, h, l);
                ah[q * 2 + 0] = h; al[q * 2 + 0] = l;
                bf16_split(f.z, f.w, h, l);
                ah[q * 2 + 1] = h; al[q * 2 + 1] = l;
            }
        }
        // ---- stage W tile 16 x 32 as [col][kpair] ----
        {
            const float* wp0 = g.W + (long long)(kk + 2 * kp8) * cH + n0 + ch * 8;
            const float* wp1 = wp0 + cH;
            float4 a0 = ((const float4*)wp0)[0], a1 = ((const float4*)wp0)[1];
            float4 b0 = ((const float4*)wp1)[0], b1 = ((const float4*)wp1)[1];
            const float e0[8] = {a0.x, a0.y, a0.z, a0.w, a1.x, a1.y, a1.z, a1.w};
            const float o0[8] = {b0.x, b0.y, b0.z, b0.w, b1.x, b1.y, b1.z, b1.w};
#pragma unroll
            for (int j = 0; j < 8; j++) {
                uint32_t h, l;
                bf16_split(e0[j], o0[j], h, l);   // (k even, k odd) for col
                Wh[(ch * 8 + j) * 9 + kp8] = h;
                Wl[(ch * 8 + j) * 9 + kp8] = l;
            }
        }
        __syncwarp();

        // ---- fragments + 3-term mma ----
        uint32_t aH[2][4], aL[2][4];
#pragma unroll
        for (int mf = 0; mf < 2; mf++) {
            int base = (mf * 16 + grp) * 9;
            aH[mf][0] = Ah[base + tig];       aL[mf][0] = Al[base + tig];
            aH[mf][1] = Ah[base + 72 + tig];  aL[mf][1] = Al[base + 72 + tig];
            aH[mf][2] = Ah[base + tig + 4];   aL[mf][2] = Al[base + tig + 4];
            aH[mf][3] = Ah[base + 72 + tig + 4]; aL[mf][3] = Al[base + 72 + tig + 4];
        }
#pragma unroll
        for (int nf = 0; nf < 4; nf++) {
            int nb = (nf * 8 + grp) * 9;
            uint32_t bH0 = Wh[nb + tig], bH1 = Wh[nb + tig + 4];
            uint32_t bL0 = Wl[nb + tig], bL1 = Wl[nb + tig + 4];
#pragma unroll
            for (int mf = 0; mf < 2; mf++) {
                float* c = acc[mf][nf];
                mma_bf(c[0], c[1], c[2], c[3],
                       aH[mf][0], aH[mf][1], aH[mf][2], aH[mf][3], bH0, bH1);
                mma_bf(c[0], c[1], c[2], c[3],
                       aH[mf][0], aH[mf][1], aH[mf][2], aH[mf][3], bL0, bL1);
                mma_bf(c[0], c[1], c[2], c[3],
                       aL[mf][0], aL[mf][1], aL[mf][2], aL[mf][3], bH0, bH1);
            }
        }
        __syncwarp();
    }

    // ---- cross-warp reduction + epilogue ----
    __syncthreads();                       // all staging reads done
    float* red = (float*)pool;             // 8 x 1024 f32
#pragma unroll
    for (int mf = 0; mf < 2; mf++)
#pragma unroll
        for (int nf = 0; nf < 4; nf++)
#pragma unroll
            for (int c = 0; c < 4; c++) {
                int row = mf * 16 + grp + ((c & 2) ? 8 : 0);
                int col = nf * 8 + tig * 2 + (c & 1);
                red[wid * 1024 + row * 32 + col] = acc[mf][nf][c];
            }
    __syncthreads();

#pragma unroll
    for (int i = 0; i < 4; i++) {
        int e = tid + (i << 8);            // 0..1023
        float v = 0.f;
#pragma unroll
        for (int w = 0; w < 8; w++) v += red[w * 1024 + e];
        int row = e >> 5, col = e & 31;
        int m = m0 + row, n = n0 + col;
        int o = m * cH + n;
        if (g.add)  v += g.add[o];
        if (g.bias) v += g.bias[n];
        if (g.mode == 0) {
            g.out[o] = sigf(v);
        } else if (g.mode == 1) {
            g.out[o] = sigf(v) * g.mul[o];
        } else if (g.mode == 2) {
            float hh = tanhf(v);
            float uu = g.u[o];
            float hn = uu * g.mul[o] + (1.0f - uu) * hh;
            g.out[o] = hn;
            if (g.out2) g.out2[o] = hn;
        } else {
            g.out[o] = v > 0.f ? v : 0.01f * v;
        }
    }
}

// ---------------------------------------------------------------------------
// Big GEMM (bf16-split tensor cores): C[m,n] = A[m,:K]@B[:K,n] + bias[n].
// Block 128x128, BK=16, 256 thr = 8 warps (4m x 2n), warp tile 32x64.
// M%128==0, K%16==0, N%4==0. remap=1: row m=(t*B+b) -> C[(b*T+t)*N+n].
// ---------------------------------------------------------------------------
__global__ __launch_bounds__(256) void big_gemm_kernel(
    const float* __restrict__ A, const float* __restrict__ Bm,
    const float* __restrict__ bias, float* __restrict__ C,
    int M, int N, int K, int remap)
{
    __shared__ uint32_t AsH[128][8], AsL[128][8];   // [m][kpair]
    __shared__ uint32_t BsH[128][9], BsL[128][9];   // [n][kpair], padded

    const int tid = threadIdx.x;
    const int m0 = blockIdx.y * 128, n0 = blockIdx.x * 128;
    const int wid = tid >> 5, lane = tid & 31;
    const int grp = lane >> 2, tig = lane & 3;
    const int wm = (wid >> 1) * 32;
    const int wn = (wid & 1) * 64;

    // global load mapping
    const int ar = tid >> 2;                   // A rows ar, ar+64
    const int kb = (tid & 3) << 1;             // A kpair base (2 pairs = 4 floats)
    const int kp = (tid >> 4) & 7;             // B kpair
    const int bn = ((tid & 15) << 2) + ((tid >> 7) << 6);  // B col base (4 cols)

    float acc[2][8][4];
#pragma unroll
    for (int mf = 0; mf < 2; mf++)
#pragma unroll
        for (int nf = 0; nf < 8; nf++)
#pragma unroll
            for (int c = 0; c < 4; c++) acc[mf][nf][c] = 0.f;

    float4 pa0, pa1, pb0, pb1;
    // prefetch k0 = 0
    {
        pa0 = *(const float4*)(A + (long long)(m0 + ar) * K + kb * 2);
        pa1 = *(const float4*)(A + (long long)(m0 + ar + 64) * K + kb * 2);
        long long r0 = (long long)(2 * kp) * N;
        int n = n0 + bn;
        if (n < N) {
            pb0 = *(const float4*)(Bm + r0 + n);
            pb1 = *(const float4*)(Bm + r0 + N + n);
        } else {
            pb0 = make_float4(0, 0, 0, 0);
            pb1 = make_float4(0, 0, 0, 0);
        }
    }

    for (int k0 = 0; k0 < K; k0 += 16) {
        // ---- store prefetched tile (split to bf16 hi/lo) ----
        {
            uint32_t h, l;
            bf16_split(pa0.x, pa0.y, h, l); AsH[ar][kb] = h;      AsL[ar][kb] = l;
            bf16_split(pa0.z, pa0.w, h, l); AsH[ar][kb + 1] = h;  AsL[ar][kb + 1] = l;
            bf16_split(pa1.x, pa1.y, h, l); AsH[ar + 64][kb] = h; AsL[ar + 64][kb] = l;
            bf16_split(pa1.z, pa1.w, h, l); AsH[ar + 64][kb + 1] = h; AsL[ar + 64][kb + 1] = l;
            bf16_split(pb0.x, pb1.x, h, l); BsH[bn + 0][kp] = h;  BsL[bn + 0][kp] = l;
            bf16_split(pb0.y, pb1.y, h, l); BsH[bn + 1][kp] = h;  BsL[bn + 1][kp] = l;
            bf16_split(pb0.z, pb1.z, h, l); BsH[bn + 2][kp] = h;  BsL[bn + 2][kp] = l;
            bf16_split(pb0.w, pb1.w, h, l); BsH[bn + 3][kp] = h;  BsL[bn + 3][kp] = l;
        }
        __syncthreads();

        // ---- prefetch next tile ----
        int kn = k0 + 16;
        if (kn < K) {
            pa0 = *(const float4*)(A + (long long)(m0 + ar) * K + kn + kb * 2);
            pa1 = *(const float4*)(A + (long long)(m0 + ar + 64) * K + kn + kb * 2);
            long long r0 = (long long)(kn + 2 * kp) * N;
            int n = n0 + bn;
            if (n < N) {
                pb0 = *(const float4*)(Bm + r0 + n);
                pb1 = *(const float4*)(Bm + r0 + N + n);
            } else {
                pb0 = make_float4(0, 0, 0, 0);
                pb1 = make_float4(0, 0, 0, 0);
            }
        }

        // ---- fragments + 3-term mma (one k16 step) ----
        uint32_t aH[2][4], aL[2][4];
#pragma unroll
        for (int mf = 0; mf < 2; mf++) {
            int mb = wm + mf * 16;
            aH[mf][0] = AsH[mb + grp][tig];        aL[mf][0] = AsL[mb + grp][tig];
            aH[mf][1] = AsH[mb + 8 + grp][tig];    aL[mf][1] = AsL[mb + 8 + grp][tig];
            aH[mf][2] = AsH[mb + grp][tig + 4];    aL[mf][2] = AsL[mb + grp][tig + 4];
            aH[mf][3] = AsH[mb + 8 + grp][tig + 4]; aL[mf][3] = AsL[mb + 8 + grp][tig + 4];
        }
#pragma unroll
        for (int nf = 0; nf < 8; nf++) {
            int nb = wn + nf * 8 + grp;
            uint32_t bH0 = BsH[nb][tig], bH1 = BsH[nb][tig + 4];
            uint32_t bL0 = BsL[nb][tig], bL1 = BsL[nb][tig + 4];
#pragma unroll
            for (int mf = 0; mf < 2; mf++) {
                float* c = acc[mf][nf];
                mma_bf(c[0], c[1], c[2], c[3],
                       aH[mf][0], aH[mf][1], aH[mf][2], aH[mf][3], bH0, bH1);
                mma_bf(c[0], c[1], c[2], c[3],
                       aH[mf][0], aH[mf][1], aH[mf][2], aH[mf][3], bL0, bL1);
                mma_bf(c[0], c[1], c[2], c[3],
                       aL[mf][0], aL[mf][1], aL[mf][2], aL[mf][3], bH0, bH1);
            }
        }
        __syncthreads();
    }

    // ---- epilogue: bias + optional [t*B+b] -> [b*T+t] row remap ----
#pragma unroll
    for (int mf = 0; mf < 2; mf++) {
        int r0 = m0 + wm + mf * 16 + grp;
        int r1 = r0 + 8;
        long long base0, base1;
        if (remap) {
            int b0r = r0 & (cB - 1), t0 = r0 >> 7;
            int b1r = r1 & (cB - 1), t1 = r1 >> 7;
            base0 = (long long)(b0r * cT + t0) * N;
            base1 = (long long)(b1r * cT + t1) * N;
        } else {
            base0 = (long long)r0 * N;
            base1 = (long long)r1 * N;
        }
#pragma unroll
        for (int nf = 0; nf < 8; nf++) {
            int n = n0 + wn + nf * 8 + tig * 2;
            if (n < N) {
                float bs0 = bias ? bias[n] : 0.f;
                float bs1 = bias ? bias[n + 1] : 0.f;
                C[base0 + n]     = acc[mf][nf][0] + bs0;
                C[base0 + n + 1] = acc[mf][nf][1] + bs1;
                C[base1 + n]     = acc[mf][nf][2] + bs0;
                C[base1 + n + 1] = acc[mf][nf][3] + bs1;
            }
        }
    }
}

__global__ void hidden_out_kernel(float* __restrict__ out) {
    int i = blockIdx.x * blockDim.x + threadIdx.x;
    if (i < cB * cH) {
        out[LOGITS_ELEMS + i] = d_h0[i];
        out[LOGITS_ELEMS + cB * cH + i] = d_h1[i];
    }
}

// ---------------------------------------------------------------------------
extern "C" void kernel_launch(void* const* d_in, const int* in_sizes, int n_in,
                              void* d_out, int out_size) {
    const long long* tok64 = (const long long*)d_in[0];
    const int*       tok32 = (const int*)d_in[0];
    const float* cnn  = (const float*)d_in[1];
    const float* emb  = (const float*)d_in[2];
    const float* Win  = (const float*)d_in[3];
    const float* bin_ = (const float*)d_in[4];
    const float* Wout = (const float*)d_in[5];
    const float* bout = (const float*)d_in[6];
    const float* Wu0  = (const float*)d_in[7];
    const float* bu0  = (const float*)d_in[8];
    const float* Wr0  = (const float*)d_in[9];
    const float* br0  = (const float*)d_in[10];
    const float* Wc0  = (const float*)d_in[11];
    const float* bc0  = (const float*)d_in[12];
    const float* Wu1  = (const float*)d_in[13];
    const float* bu1  = (const float*)d_in[14];
    const float* Wr1  = (const float*)d_in[15];
    const float* br1  = (const float*)d_in[16];
    const float* Wc1  = (const float*)d_in[17];
    const float* bc1  = (const float*)d_in[18];
    float* out = (float*)d_out;

    float *pP, *pX, *pA0u, *pA0r, *pA0c, *pH1, *ph0, *ph1, *pU0, *pRH0, *pU1, *pRH1;
    cudaGetSymbolAddress((void**)&pP,   d_P);
    cudaGetSymbolAddress((void**)&pX,   d_X);
    cudaGetSymbolAddress((void**)&pA0u, d_A0u);
    cudaGetSymbolAddress((void**)&pA0r, d_A0r);
    cudaGetSymbolAddress((void**)&pA0c, d_A0c);
    cudaGetSymbolAddress((void**)&pH1,  d_H1);
    cudaGetSymbolAddress((void**)&ph0,  d_h0);
    cudaGetSymbolAddress((void**)&ph1,  d_h1);
    cudaGetSymbolAddress((void**)&pU0,  d_U0);
    cudaGetSymbolAddress((void**)&pRH0, d_RH0);
    cudaGetSymbolAddress((void**)&pU1,  d_U1);
    cudaGetSymbolAddress((void**)&pRH1, d_RH1);

    detect_tok_kernel<<<1, 256>>>(tok64);
    init_h_kernel<<<(cB * cH + 255) / 256, 256>>>();

    // input layer: P = leaky_relu(cnn @ Win + bin)   (K=2048, mode 3)
    RArgs gin = {cnn, nullptr, Win, nullptr, bin_, nullptr, nullptr,
                 pP, nullptr, cNF, cNF, 3};
    rec_gemm_kernel<<<dim3(4, 16, 1), 256>>>(gin, gin);

    gather_x_kernel<<<(cTB * cIN0 / 4 + 255) / 256, 256>>>(tok64, tok32, emb);

    // precompute input-dependent gate terms: A0* = X @ W[x-rows] + bias
    dim3 gpre(cH / 128, cTB / 128);
    big_gemm_kernel<<<gpre, 256>>>(pX, Wu0,           bu0, pA0u, cTB, cH, cIN0, 0);
    big_gemm_kernel<<<gpre, 256>>>(pX, Wr0,           br0, pA0r, cTB, cH, cIN0, 0);
    big_gemm_kernel<<<gpre, 256>>>(pX, Wc0 + cH * cH, bc0, pA0c, cTB, cH, cIN0, 0);

    // recurrent loop: xh=[x,h]; cand0=[r0*h0, x]; cand1=[r1*h1, h0]
    for (int t = 0; t < cT; t++) {
        const float* a0u = pA0u + t * cB * cH;
        const float* a0r = pA0r + t * cB * cH;
        const float* a0c = pA0c + t * cB * cH;

        RArgs g_u0 = {ph0, nullptr, Wu0 + cIN0 * cH, a0u, nullptr, nullptr, nullptr,
                      pU0, nullptr, cH, cH, 0};
        RArgs g_r0 = {ph0, nullptr, Wr0 + cIN0 * cH, a0r, nullptr, ph0, nullptr,
                      pRH0, nullptr, cH, cH, 1};
        rec_gemm_kernel<<<dim3(4, 16, 2), 256>>>(g_u0, g_r0);

        RArgs g_c0 = {pRH0, nullptr, Wc0, a0c, nullptr, ph0, pU0,
                      ph0, nullptr, cH, cH, 2};
        rec_gemm_kernel<<<dim3(4, 16, 1), 256>>>(g_c0, g_c0);

        RArgs g_u1 = {ph0, ph1, Wu1, nullptr, bu1, nullptr, nullptr,
                      pU1, nullptr, 2 * cH, cH, 0};
        RArgs g_r1 = {ph0, ph1, Wr1, nullptr, br1, ph1, nullptr,
                      pRH1, nullptr, 2 * cH, cH, 1};
        rec_gemm_kernel<<<dim3(4, 16, 2), 256>>>(g_u1, g_r1);

        RArgs g_c1 = {pRH1, ph0, Wc1, nullptr, bc1, ph1, pU1,
                      ph1, pH1 + t * cB * cH, 2 * cH, cH, 2};
        rec_gemm_kernel<<<dim3(4, 16, 1), 256>>>(g_c1, g_c1);
    }

    // logits = H1all @ Wout + bout, written in [B, T, V] layout
    big_gemm_kernel<<<dim3((cV + 127) / 128, cTB / 128), 256>>>(
        pH1, Wout, bout, out, cTB, cV, cH, 1);

    hidden_out_kernel<<<(cB * cH + 255) / 256, 256>>>(out);
}

// round 7
// speedup vs baseline: 1.2147x; 1.2147x over previous
#include <cuda_runtime.h>
#include <cuda_bf16.h>
#include <math.h>
#include <stdint.h>

// ---------------------------------------------------------------------------
// ImageCaptionModel GRU decoder. B=128,T=25,V=10000,E=512,NF=2048,H=512.
// One-time bf16 hi/lo packing of all GEMM operands + persistent recurrent
// kernel with grid barriers (1 launch for all 25 steps).
// Math: 3-pass bf16-split mma.m16n8k16 (AhiBhi+AhiBlo+AloBhi, fp32 acc).
// ---------------------------------------------------------------------------

namespace {
constexpr int cB = 128, cT = 25, cV = 10000, cE = 512, cNF = 2048;
constexpr int cH = 512, cMAP = 512, cTB = cB * cT;
constexpr long long LOGITS_ELEMS = (long long)cB * cT * cV;
}

// -------- scratch (__device__ globals; no allocation allowed) --------------
__device__ float d_P[cB * cMAP];
__device__ uint32_t d_CH[cB * 1024], d_CL[cB * 1024];          // cnn packed
__device__ uint32_t d_WinH[1024 * 512], d_WinL[1024 * 512];
__device__ uint32_t d_XH[cTB * 512], d_XL[cTB * 512];          // X packed [m][kp]
__device__ float d_A0u[cTB * cH], d_A0r[cTB * cH], d_A0c[cTB * cH];
__device__ uint32_t d_H1H[cTB * 256], d_H1L[cTB * 256];
__device__ float d_h0f[cB * cH], d_h1f[cB * cH];
__device__ float d_U0[cB * cH], d_U1[cB * cH];
__device__ uint32_t d_h0pH[cB * 256], d_h0pL[cB * 256];
__device__ uint32_t d_h1pH[cB * 256], d_h1pL[cB * 256];
__device__ uint32_t d_RH0H[cB * 256], d_RH0L[cB * 256];
__device__ uint32_t d_RH1H[cB * 256], d_RH1L[cB * 256];
// k-major packed weights [kp][N]
__device__ uint32_t d_Wu0xH[512 * 512], d_Wu0xL[512 * 512];
__device__ uint32_t d_Wr0xH[512 * 512], d_Wr0xL[512 * 512];
__device__ uint32_t d_Wc0xH[512 * 512], d_Wc0xL[512 * 512];
__device__ uint32_t d_WoutH[256 * 10000], d_WoutL[256 * 10000];
// n-major packed weights [n][kp]
__device__ uint32_t d_WU0hH[512 * 256], d_WU0hL[512 * 256];
__device__ uint32_t d_WR0hH[512 * 256], d_WR0hL[512 * 256];
__device__ uint32_t d_WC0rhH[512 * 256], d_WC0rhL[512 * 256];
__device__ uint32_t d_WU1H[512 * 512], d_WU1L[512 * 512];
__device__ uint32_t d_WR1H[512 * 512], d_WR1L[512 * 512];
__device__ uint32_t d_WC1H[512 * 512], d_WC1L[512 * 512];
__device__ int d_tok64;
__device__ unsigned g_cnt = 0;
__device__ volatile unsigned g_gen = 0;

// -------- helpers ----------------------------------------------------------
__device__ __forceinline__ float sigf(float x) { return 1.0f / (1.0f + __expf(-x)); }

__device__ __forceinline__ void bf16_split(float a, float b, uint32_t& hi, uint32_t& lo) {
    __nv_bfloat162 h;
    h.x = __float2bfloat16_rn(a);
    h.y = __float2bfloat16_rn(b);
    __nv_bfloat162 l;
    l.x = __float2bfloat16_rn(a - __bfloat162float(h.x));
    l.y = __float2bfloat16_rn(b - __bfloat162float(h.y));
    hi = *reinterpret_cast<uint32_t*>(&h);
    lo = *reinterpret_cast<uint32_t*>(&l);
}

__device__ __forceinline__ void mma_bf(
    float& c0, float& c1, float& c2, float& c3,
    uint32_t a0, uint32_t a1, uint32_t a2, uint32_t a3,
    uint32_t b0, uint32_t b1)
{
    asm volatile(
        "mma.sync.aligned.m16n8k16.row.col.f32.bf16.bf16.f32 "
        "{%0,%1,%2,%3}, {%4,%5,%6,%7}, {%8,%9}, {%0,%1,%2,%3};\n"
        : "+f"(c0), "+f"(c1), "+f"(c2), "+f"(c3)
        : "r"(a0), "r"(a1), "r"(a2), "r"(a3), "r"(b0), "r"(b1));
}

// -------- utility kernels --------------------------------------------------
__global__ void detect_tok_kernel(const long long* __restrict__ t) {
    __shared__ int bad;
    if (threadIdx.x == 0) bad = 0;
    __syncthreads();
    for (int i = threadIdx.x; i < cTB / 2; i += blockDim.x) {
        long long v = t[i];
        if (v < 0 || v >= (long long)cV) bad = 1;
    }
    __syncthreads();
    if (threadIdx.x == 0) d_tok64 = (bad == 0) ? 1 : 0;
}

__global__ void init_all_kernel() {
    int i = blockIdx.x * blockDim.x + threadIdx.x;
    if (i < cB * cH) { d_h0f[i] = 0.f; d_h1f[i] = 0.f; }
    if (i < cB * 256) {
        d_h0pH[i] = 0u; d_h0pL[i] = 0u;
        d_h1pH[i] = 0u; d_h1pL[i] = 0u;
    }
}

// pack fp32 row-major A [M, 2*K2] -> [M][K2] hi/lo
__global__ void pack_a_kernel(const float* __restrict__ src, uint32_t* __restrict__ oh,
                              uint32_t* __restrict__ ol, int M, int K2) {
    int idx = blockIdx.x * blockDim.x + threadIdx.x;
    if (idx >= M * K2) return;
    int m = idx / K2, kp = idx - m * K2;
    uint32_t h, l;
    float2 v = *(const float2*)(src + (long long)m * (2 * K2) + 2 * kp);
    bf16_split(v.x, v.y, h, l);
    oh[idx] = h; ol[idx] = l;
}

// pack fp32 [2*K2, N] (row stride ld) -> k-major [K2][N]
__global__ void pack_b_kernel(const float* __restrict__ src, uint32_t* __restrict__ oh,
                              uint32_t* __restrict__ ol, int K2, int N, int ld) {
    int idx = blockIdx.x * blockDim.x + threadIdx.x;
    if (idx >= K2 * N) return;
    int kp = idx / N, n = idx - kp * N;
    uint32_t h, l;
    bf16_split(src[(long long)(2 * kp) * ld + n], src[(long long)(2 * kp + 1) * ld + n], h, l);
    oh[idx] = h; ol[idx] = l;
}

// pack fp32 [2*K2, 512] -> n-major [512][K2]
__global__ void pack_bt_kernel(const float* __restrict__ src, uint32_t* __restrict__ oh,
                               uint32_t* __restrict__ ol, int K2) {
    int idx = blockIdx.x * blockDim.x + threadIdx.x;
    if (idx >= 512 * K2) return;
    int n = idx / K2, kp = idx - n * K2;
    uint32_t h, l;
    bf16_split(src[(2 * kp) * cH + n], src[(2 * kp + 1) * cH + n], h, l);
    oh[idx] = h; ol[idx] = l;
}

// X packed: row m=t*B+b, kp<256 -> emb pair, else P pair
__global__ void gather_pack_kernel(const long long* __restrict__ tok64,
                                   const int* __restrict__ tok32,
                                   const float* __restrict__ emb) {
    int idx = blockIdx.x * blockDim.x + threadIdx.x;
    if (idx >= cTB * 512) return;
    int m = idx >> 9, kp = idx & 511;
    int tt = m / cB, b = m % cB;
    int tok = d_tok64 ? (int)tok64[b * cT + tt] : tok32[b * cT + tt];
    float2 v;
    if (kp < 256) v = *(const float2*)(emb + (long long)tok * cE + 2 * kp);
    else          v = *(const float2*)(d_P + b * cMAP + 2 * (kp - 256));
    uint32_t h, l;
    bf16_split(v.x, v.y, h, l);
    d_XH[idx] = h; d_XL[idx] = l;
}

// ---------------------------------------------------------------------------
// Staged big GEMM on pre-packed operands: C = A@B + bias (3-pass split).
// A packed [M][as] hi/lo; B packed k-major [K/2][N]. Block 128x128, BK=16.
// act: 0 none, 1 leaky. remap=1: logits [B,T,V] layout.
// ---------------------------------------------------------------------------
__global__ __launch_bounds__(256) void big_gemm_pre(
    const uint32_t* __restrict__ AH, const uint32_t* __restrict__ AL, int as,
    const uint32_t* __restrict__ BH, const uint32_t* __restrict__ BL,
    const float* __restrict__ bias, float* __restrict__ C,
    int N, int K, int act, int remap)
{
    __shared__ uint32_t AsH[128][8], AsL[128][8];
    __shared__ uint32_t BsH[128][9], BsL[128][9];
    const int tid = threadIdx.x;
    const int m0 = blockIdx.y * 128, n0 = blockIdx.x * 128;
    const int wid = tid >> 5, lane = tid & 31;
    const int grp = lane >> 2, tig = lane & 3;
    const int wm = (wid >> 1) * 32, wn = (wid & 1) * 64;
    const int ar = tid >> 2, kb = (tid & 3) << 1;
    const int kp = (tid >> 4) & 7;
    const int bn = ((tid & 15) << 2) + ((tid >> 7) << 6);

    float acc[2][8][4] = {};
    uint2 a0h, a0l, a1h, a1l;
    uint4 bh, bl;
    {
        const uint32_t* pa = AH + (long long)(m0 + ar) * as + kb;
        const uint32_t* pl = AL + (long long)(m0 + ar) * as + kb;
        a0h = *(const uint2*)pa; a1h = *(const uint2*)(pa + (long long)64 * as);
        a0l = *(const uint2*)pl; a1l = *(const uint2*)(pl + (long long)64 * as);
        int n = n0 + bn;
        if (n < N) {
            bh = *(const uint4*)(BH + (long long)kp * N + n);
            bl = *(const uint4*)(BL + (long long)kp * N + n);
        } else { bh = make_uint4(0, 0, 0, 0); bl = bh; }
    }

    for (int k0 = 0; k0 < K; k0 += 16) {
        AsH[ar][kb] = a0h.x; AsH[ar][kb + 1] = a0h.y;
        AsH[ar + 64][kb] = a1h.x; AsH[ar + 64][kb + 1] = a1h.y;
        AsL[ar][kb] = a0l.x; AsL[ar][kb + 1] = a0l.y;
        AsL[ar + 64][kb] = a1l.x; AsL[ar + 64][kb + 1] = a1l.y;
        BsH[bn + 0][kp] = bh.x; BsH[bn + 1][kp] = bh.y;
        BsH[bn + 2][kp] = bh.z; BsH[bn + 3][kp] = bh.w;
        BsL[bn + 0][kp] = bl.x; BsL[bn + 1][kp] = bl.y;
        BsL[bn + 2][kp] = bl.z; BsL[bn + 3][kp] = bl.w;
        __syncthreads();

        int kn = k0 + 16;
        if (kn < K) {
            const uint32_t* pa = AH + (long long)(m0 + ar) * as + kn / 2 + kb;
            const uint32_t* pl = AL + (long long)(m0 + ar) * as + kn / 2 + kb;
            a0h = *(const uint2*)pa; a1h = *(const uint2*)(pa + (long long)64 * as);
            a0l = *(const uint2*)pl; a1l = *(const uint2*)(pl + (long long)64 * as);
            int n = n0 + bn;
            if (n < N) {
                bh = *(const uint4*)(BH + (long long)(kn / 2 + kp) * N + n);
                bl = *(const uint4*)(BL + (long long)(kn / 2 + kp) * N + n);
            } else { bh = make_uint4(0, 0, 0, 0); bl = bh; }
        }

        uint32_t aHf[2][4], aLf[2][4];
#pragma unroll
        for (int mf = 0; mf < 2; mf++) {
            int mb = wm + mf * 16;
            aHf[mf][0] = AsH[mb + grp][tig];         aLf[mf][0] = AsL[mb + grp][tig];
            aHf[mf][1] = AsH[mb + 8 + grp][tig];     aLf[mf][1] = AsL[mb + 8 + grp][tig];
            aHf[mf][2] = AsH[mb + grp][tig + 4];     aLf[mf][2] = AsL[mb + grp][tig + 4];
            aHf[mf][3] = AsH[mb + 8 + grp][tig + 4]; aLf[mf][3] = AsL[mb + 8 + grp][tig + 4];
        }
#pragma unroll
        for (int nf = 0; nf < 8; nf++) {
            int nb = wn + nf * 8 + grp;
            uint32_t b0H = BsH[nb][tig], b1H = BsH[nb][tig + 4];
            uint32_t b0L = BsL[nb][tig], b1L = BsL[nb][tig + 4];
#pragma unroll
            for (int mf = 0; mf < 2; mf++) {
                float* c = acc[mf][nf];
                mma_bf(c[0], c[1], c[2], c[3],
                       aHf[mf][0], aHf[mf][1], aHf[mf][2], aHf[mf][3], b0H, b1H);
                mma_bf(c[0], c[1], c[2], c[3],
                       aHf[mf][0], aHf[mf][1], aHf[mf][2], aHf[mf][3], b0L, b1L);
                mma_bf(c[0], c[1], c[2], c[3],
                       aLf[mf][0], aLf[mf][1], aLf[mf][2], aLf[mf][3], b0H, b1H);
            }
        }
        __syncthreads();
    }

#pragma unroll
    for (int mf = 0; mf < 2; mf++) {
        int r0 = m0 + wm + mf * 16 + grp;
        int r1 = r0 + 8;
        long long base0, base1;
        if (remap) {
            int b0r = r0 & (cB - 1), t0 = r0 >> 7;
            int b1r = r1 & (cB - 1), t1 = r1 >> 7;
            base0 = (long long)(b0r * cT + t0) * N;
            base1 = (long long)(b1r * cT + t1) * N;
        } else {
            base0 = (long long)r0 * N;
            base1 = (long long)r1 * N;
        }
#pragma unroll
        for (int nf = 0; nf < 8; nf++) {
            int n = n0 + wn + nf * 8 + tig * 2;
            if (n < N) {
                float o00 = acc[mf][nf][0] + bias[n];
                float o01 = acc[mf][nf][1] + bias[n + 1];
                float o10 = acc[mf][nf][2] + bias[n];
                float o11 = acc[mf][nf][3] + bias[n + 1];
                if (act == 1) {
                    o00 = o00 > 0.f ? o00 : 0.01f * o00;
                    o01 = o01 > 0.f ? o01 : 0.01f * o01;
                    o10 = o10 > 0.f ? o10 : 0.01f * o10;
                    o11 = o11 > 0.f ? o11 : 0.01f * o11;
                }
                C[base0 + n] = o00; C[base0 + n + 1] = o01;
                C[base1 + n] = o10; C[base1 + n + 1] = o11;
            }
        }
    }
}

// ---------------------------------------------------------------------------
// Persistent recurrent kernel: 128 blocks (all wave-1 resident on 148 SMs),
// 3 grid barriers per step (barrier after phase D elided: conflict-free).
// ---------------------------------------------------------------------------
__device__ __forceinline__ void grid_bar() {
    __syncthreads();
    if (threadIdx.x == 0) {
        unsigned gen = g_gen;
        __threadfence();                       // release block's prior stores
        if (atomicAdd(&g_cnt, 1u) == 127u) {
            atomicExch(&g_cnt, 0u);            // L2-atomic reset, fence-ordered
            __threadfence();
            g_gen = gen + 1;
        } else {
            while (g_gen == gen) { }
        }
        __threadfence();                       // acquire
    }
    __syncthreads();
}

// warp split-K GEMM tile; A packed stride 256 words, direct gmem fragments.
template <int NITER, int MF>
__device__ __forceinline__ void tile_gemm(
    const uint32_t* __restrict__ AH, const uint32_t* __restrict__ AL, int kpa0,
    const uint32_t* __restrict__ BH, const uint32_t* __restrict__ BL, int bs, int kpb0,
    int m0, int n0, int grp, int tig, float (&acc)[MF][4][4])
{
#pragma unroll
    for (int it = 0; it < NITER; it++) {
        const int kpA = kpa0 + it * 8, kpB = kpb0 + it * 8;
        uint32_t aH[MF][4], aL[MF][4];
#pragma unroll
        for (int mf = 0; mf < MF; mf++) {
            const int r = (m0 + mf * 16 + grp) * 256 + kpA;
            aH[mf][0] = __ldcg(AH + r + tig);        aH[mf][1] = __ldcg(AH + r + 2048 + tig);
            aH[mf][2] = __ldcg(AH + r + tig + 4);    aH[mf][3] = __ldcg(AH + r + 2048 + tig + 4);
            aL[mf][0] = __ldcg(AL + r + tig);        aL[mf][1] = __ldcg(AL + r + 2048 + tig);
            aL[mf][2] = __ldcg(AL + r + tig + 4);    aL[mf][3] = __ldcg(AL + r + 2048 + tig + 4);
        }
#pragma unroll
        for (int nf = 0; nf < 4; nf++) {
            const int nb = (n0 + nf * 8 + grp) * bs + kpB;
            uint32_t b0H = __ldg(BH + nb + tig), b1H = __ldg(BH + nb + tig + 4);
            uint32_t b0L = __ldg(BL + nb + tig), b1L = __ldg(BL + nb + tig + 4);
#pragma unroll
            for (int mf = 0; mf < MF; mf++) {
                float* c = acc[mf][nf];
                mma_bf(c[0], c[1], c[2], c[3],
                       aH[mf][0], aH[mf][1], aH[mf][2], aH[mf][3], b0H, b1H);
                mma_bf(c[0], c[1], c[2], c[3],
                       aH[mf][0], aH[mf][1], aH[mf][2], aH[mf][3], b0L, b1L);
                mma_bf(c[0], c[1], c[2], c[3],
                       aL[mf][0], aL[mf][1], aL[mf][2], aL[mf][3], b0H, b1H);
            }
        }
    }
}

template <int MF>
__device__ __forceinline__ void store_red(float (*red)[1024], float (&acc)[MF][4][4],
                                          int wid, int grp, int tig) {
#pragma unroll
    for (int mf = 0; mf < MF; mf++)
#pragma unroll
        for (int nf = 0; nf < 4; nf++) {
            int c = nf * 8 + tig * 2, r = mf * 16 + grp;
            red[wid][r * 32 + c] = acc[mf][nf][0];
            red[wid][r * 32 + c + 1] = acc[mf][nf][1];
            red[wid][(r + 8) * 32 + c] = acc[mf][nf][2];
            red[wid][(r + 8) * 32 + c + 1] = acc[mf][nf][3];
        }
}

__device__ __forceinline__ float4 sum_red4(float (*red)[1024], int e0) {
    float4 s = make_float4(0, 0, 0, 0);
#pragma unroll
    for (int w = 0; w < 8; w++) {
        float4 r = *(float4*)&red[w][e0];
        s.x += r.x; s.y += r.y; s.z += r.z; s.w += r.w;
    }
    return s;
}

__device__ __forceinline__ float2 sum_red2(float (*red)[1024], int e0) {
    float2 s = make_float2(0, 0);
#pragma unroll
    for (int w = 0; w < 8; w++) {
        float2 r = *(float2*)&red[w][e0];
        s.x += r.x; s.y += r.y;
    }
    return s;
}

__global__ __launch_bounds__(256) void loop_kernel(
    const float* __restrict__ bu1, const float* __restrict__ br1,
    const float* __restrict__ bc1)
{
    __shared__ float red[8][1024];
    const int tid = threadIdx.x, wid = tid >> 5, lane = tid & 31;
    const int grp = lane >> 2, tig = lane & 3;
    const int blk = blockIdx.x;

    for (int t = 0; t < cT; t++) {
        // ---- phase A: u0 (blk<64) / r0 (blk>=64), 32x32 tiles, K=512 ----
        {
            int gate = blk >> 6, tile = blk & 63;
            int m0 = (tile & 3) * 32, n0 = (tile >> 2) * 32;
            float acc[2][4][4] = {};
            tile_gemm<4, 2>(d_h0pH, d_h0pL, wid * 32,
                            gate ? d_WR0hH : d_WU0hH, gate ? d_WR0hL : d_WU0hL,
                            256, wid * 32, m0, n0, grp, tig, acc);
            store_red<2>(red, acc, wid, grp, tig);
            __syncthreads();
            const float* A0 = (gate ? d_A0r : d_A0u) + t * cB * cH;
            int e0 = tid * 4;
            float4 s = sum_red4(red, e0);
            int m = m0 + (e0 >> 5), n = n0 + (e0 & 31), o = m * cH + n;
            float4 a = *(const float4*)(A0 + o);
            if (gate == 0) {
                d_U0[o] = sigf(a.x + s.x);     d_U0[o + 1] = sigf(a.y + s.y);
                d_U0[o + 2] = sigf(a.z + s.z); d_U0[o + 3] = sigf(a.w + s.w);
            } else {
                float r0 = sigf(a.x + s.x) * __ldcg(d_h0f + o);
                float r1 = sigf(a.y + s.y) * __ldcg(d_h0f + o + 1);
                float r2 = sigf(a.z + s.z) * __ldcg(d_h0f + o + 2);
                float r3 = sigf(a.w + s.w) * __ldcg(d_h0f + o + 3);
                uint32_t h, l;
                int kp = m * 256 + (n >> 1);
                bf16_split(r0, r1, h, l); d_RH0H[kp] = h;     d_RH0L[kp] = l;
                bf16_split(r2, r3, h, l); d_RH0H[kp + 1] = h; d_RH0L[kp + 1] = l;
            }
        }
        grid_bar();
        // ---- phase B: c0, 16x32 tiles, K=512, in-place h0 update ----
        {
            int m0 = (blk & 7) * 16, n0 = (blk >> 3) * 32;
            float acc[1][4][4] = {};
            tile_gemm<4, 1>(d_RH0H, d_RH0L, wid * 32,
                            d_WC0rhH, d_WC0rhL, 256, wid * 32, m0, n0, grp, tig, acc);
            store_red<1>(red, acc, wid, grp, tig);
            __syncthreads();
            const float* A0 = d_A0c + t * cB * cH;
            int e0 = tid * 2;
            float2 s = sum_red2(red, e0);
            int m = m0 + (e0 >> 5), n = n0 + (e0 & 31), o = m * cH + n;
            float v0 = A0[o] + s.x, v1 = A0[o + 1] + s.y;
            float u0 = __ldcg(d_U0 + o), u1 = __ldcg(d_U0 + o + 1);
            float p0 = __ldcg(d_h0f + o), p1 = __ldcg(d_h0f + o + 1);
            float n0v = u0 * p0 + (1.f - u0) * tanhf(v0);
            float n1v = u1 * p1 + (1.f - u1) * tanhf(v1);
            d_h0f[o] = n0v; d_h0f[o + 1] = n1v;
            uint32_t h, l;
            bf16_split(n0v, n1v, h, l);
            int kp = m * 256 + (n >> 1);
            d_h0pH[kp] = h; d_h0pL[kp] = l;
        }
        grid_bar();
        // ---- phase C: u1 / r1, 32x32 tiles, K=1024 ([h0,h1]) ----
        {
            int gate = blk >> 6, tile = blk & 63;
            int m0 = (tile & 3) * 32, n0 = (tile >> 2) * 32;
            float acc[2][4][4] = {};
            tile_gemm<8, 2>((wid < 4) ? d_h0pH : d_h1pH, (wid < 4) ? d_h0pL : d_h1pL,
                            (wid & 3) * 64,
                            gate ? d_WR1H : d_WU1H, gate ? d_WR1L : d_WU1L,
                            512, wid * 64, m0, n0, grp, tig, acc);
            store_red<2>(red, acc, wid, grp, tig);
            __syncthreads();
            const float* bb = gate ? br1 : bu1;
            int e0 = tid * 4;
            float4 s = sum_red4(red, e0);
            int m = m0 + (e0 >> 5), n = n0 + (e0 & 31), o = m * cH + n;
            float4 b = *(const float4*)(bb + n);
            if (gate == 0) {
                d_U1[o] = sigf(b.x + s.x);     d_U1[o + 1] = sigf(b.y + s.y);
                d_U1[o + 2] = sigf(b.z + s.z); d_U1[o + 3] = sigf(b.w + s.w);
            } else {
                float r0 = sigf(b.x + s.x) * __ldcg(d_h1f + o);
                float r1 = sigf(b.y + s.y) * __ldcg(d_h1f + o + 1);
                float r2 = sigf(b.z + s.z) * __ldcg(d_h1f + o + 2);
                float r3 = sigf(b.w + s.w) * __ldcg(d_h1f + o + 3);
                uint32_t h, l;
                int kp = m * 256 + (n >> 1);
                bf16_split(r0, r1, h, l); d_RH1H[kp] = h;     d_RH1L[kp] = l;
                bf16_split(r2, r3, h, l); d_RH1H[kp + 1] = h; d_RH1L[kp + 1] = l;
            }
        }
        grid_bar();
        // ---- phase D: c1, 16x32 tiles, K=1024 ([RH1,h0]); no barrier after
        //      (conflict-free with next phase A; ordered transitively) ----
        {
            int m0 = (blk & 7) * 16, n0 = (blk >> 3) * 32;
            float acc[1][4][4] = {};
            tile_gemm<8, 1>((wid < 4) ? d_RH1H : d_h0pH, (wid < 4) ? d_RH1L : d_h0pL,
                            (wid & 3) * 64,
                            d_WC1H, d_WC1L, 512, wid * 64, m0, n0, grp, tig, acc);
            store_red<1>(red, acc, wid, grp, tig);
            __syncthreads();
            int e0 = tid * 2;
            float2 s = sum_red2(red, e0);
            int m = m0 + (e0 >> 5), n = n0 + (e0 & 31), o = m * cH + n;
            float v0 = bc1[n] + s.x, v1 = bc1[n + 1] + s.y;
            float u0 = __ldcg(d_U1 + o), u1 = __ldcg(d_U1 + o + 1);
            float p0 = __ldcg(d_h1f + o), p1 = __ldcg(d_h1f + o + 1);
            float n0v = u0 * p0 + (1.f - u0) * tanhf(v0);
            float n1v = u1 * p1 + (1.f - u1) * tanhf(v1);
            d_h1f[o] = n0v; d_h1f[o + 1] = n1v;
            uint32_t h, l;
            bf16_split(n0v, n1v, h, l);
            int kp = m * 256 + (n >> 1);
            d_h1pH[kp] = h; d_h1pL[kp] = l;
            long long hp = (long long)(t * cB + m) * 256 + (n >> 1);
            d_H1H[hp] = h; d_H1L[hp] = l;
            __syncthreads();   // red reuse next phase A
        }
    }
}

__global__ void hidden_out_kernel(float* __restrict__ out) {
    int i = blockIdx.x * blockDim.x + threadIdx.x;
    if (i < cB * cH) {
        out[LOGITS_ELEMS + i] = d_h0f[i];
        out[LOGITS_ELEMS + cB * cH + i] = d_h1f[i];
    }
}

// ---------------------------------------------------------------------------
extern "C" void kernel_launch(void* const* d_in, const int* in_sizes, int n_in,
                              void* d_out, int out_size) {
    const long long* tok64 = (const long long*)d_in[0];
    const int*       tok32 = (const int*)d_in[0];
    const float* cnn  = (const float*)d_in[1];
    const float* emb  = (const float*)d_in[2];
    const float* Win  = (const float*)d_in[3];
    const float* bin_ = (const float*)d_in[4];
    const float* Wout = (const float*)d_in[5];
    const float* bout = (const float*)d_in[6];
    const float* Wu0  = (const float*)d_in[7];
    const float* bu0  = (const float*)d_in[8];
    const float* Wr0  = (const float*)d_in[9];
    const float* br0  = (const float*)d_in[10];
    const float* Wc0  = (const float*)d_in[11];
    const float* bc0  = (const float*)d_in[12];
    const float* Wu1  = (const float*)d_in[13];
    const float* bu1  = (const float*)d_in[14];
    const float* Wr1  = (const float*)d_in[15];
    const float* br1  = (const float*)d_in[16];
    const float* Wc1  = (const float*)d_in[17];
    const float* bc1  = (const float*)d_in[18];
    float* out = (float*)d_out;

    float *pP, *pA0u, *pA0r, *pA0c;
    uint32_t *pCH, *pCL, *pWinH, *pWinL, *pXH, *pXL;
    uint32_t *pWu0xH, *pWu0xL, *pWr0xH, *pWr0xL, *pWc0xH, *pWc0xL;
    uint32_t *pWoutH, *pWoutL, *pH1H, *pH1L;
    uint32_t *pWU0hH, *pWU0hL, *pWR0hH, *pWR0hL, *pWC0rhH, *pWC0rhL;
    uint32_t *pWU1H, *pWU1L, *pWR1H, *pWR1L, *pWC1H, *pWC1L;
    cudaGetSymbolAddress((void**)&pP, d_P);
    cudaGetSymbolAddress((void**)&pA0u, d_A0u);
    cudaGetSymbolAddress((void**)&pA0r, d_A0r);
    cudaGetSymbolAddress((void**)&pA0c, d_A0c);
    cudaGetSymbolAddress((void**)&pCH, d_CH);
    cudaGetSymbolAddress((void**)&pCL, d_CL);
    cudaGetSymbolAddress((void**)&pWinH, d_WinH);
    cudaGetSymbolAddress((void**)&pWinL, d_WinL);
    cudaGetSymbolAddress((void**)&pXH, d_XH);
    cudaGetSymbolAddress((void**)&pXL, d_XL);
    cudaGetSymbolAddress((void**)&pWu0xH, d_Wu0xH);
    cudaGetSymbolAddress((void**)&pWu0xL, d_Wu0xL);
    cudaGetSymbolAddress((void**)&pWr0xH, d_Wr0xH);
    cudaGetSymbolAddress((void**)&pWr0xL, d_Wr0xL);
    cudaGetSymbolAddress((void**)&pWc0xH, d_Wc0xH);
    cudaGetSymbolAddress((void**)&pWc0xL, d_Wc0xL);
    cudaGetSymbolAddress((void**)&pWoutH, d_WoutH);
    cudaGetSymbolAddress((void**)&pWoutL, d_WoutL);
    cudaGetSymbolAddress((void**)&pH1H, d_H1H);
    cudaGetSymbolAddress((void**)&pH1L, d_H1L);
    cudaGetSymbolAddress((void**)&pWU0hH, d_WU0hH);
    cudaGetSymbolAddress((void**)&pWU0hL, d_WU0hL);
    cudaGetSymbolAddress((void**)&pWR0hH, d_WR0hH);
    cudaGetSymbolAddress((void**)&pWR0hL, d_WR0hL);
    cudaGetSymbolAddress((void**)&pWC0rhH, d_WC0rhH);
    cudaGetSymbolAddress((void**)&pWC0rhL, d_WC0rhL);
    cudaGetSymbolAddress((void**)&pWU1H, d_WU1H);
    cudaGetSymbolAddress((void**)&pWU1L, d_WU1L);
    cudaGetSymbolAddress((void**)&pWR1H, d_WR1H);
    cudaGetSymbolAddress((void**)&pWR1L, d_WR1L);
    cudaGetSymbolAddress((void**)&pWC1H, d_WC1H);
    cudaGetSymbolAddress((void**)&pWC1L, d_WC1L);

    detect_tok_kernel<<<1, 256>>>(tok64);
    init_all_kernel<<<(cB * cH + 255) / 256, 256>>>();

    // ---- one-time packing ----
    pack_a_kernel<<<(cB * 1024 + 255) / 256, 256>>>(cnn, pCH, pCL, cB, 1024);
    pack_b_kernel<<<(1024 * 512 + 255) / 256, 256>>>(Win, pWinH, pWinL, 1024, 512, 512);
    pack_b_kernel<<<(512 * 512 + 255) / 256, 256>>>(Wu0, pWu0xH, pWu0xL, 512, 512, 512);
    pack_b_kernel<<<(512 * 512 + 255) / 256, 256>>>(Wr0, pWr0xH, pWr0xL, 512, 512, 512);
    pack_b_kernel<<<(512 * 512 + 255) / 256, 256>>>(Wc0 + 512 * 512, pWc0xH, pWc0xL, 512, 512, 512);
    pack_b_kernel<<<(256 * 10000 + 255) / 256, 256>>>(Wout, pWoutH, pWoutL, 256, 10000, 10000);
    pack_bt_kernel<<<(512 * 256 + 255) / 256, 256>>>(Wu0 + 1024 * 512, pWU0hH, pWU0hL, 256);
    pack_bt_kernel<<<(512 * 256 + 255) / 256, 256>>>(Wr0 + 1024 * 512, pWR0hH, pWR0hL, 256);
    pack_bt_kernel<<<(512 * 256 + 255) / 256, 256>>>(Wc0, pWC0rhH, pWC0rhL, 256);
    pack_bt_kernel<<<(512 * 512 + 255) / 256, 256>>>(Wu1, pWU1H, pWU1L, 512);
    pack_bt_kernel<<<(512 * 512 + 255) / 256, 256>>>(Wr1, pWR1H, pWR1L, 512);
    pack_bt_kernel<<<(512 * 512 + 255) / 256, 256>>>(Wc1, pWC1H, pWC1L, 512);

    // ---- input layer: P = leaky(cnn @ Win + bin) ----
    big_gemm_pre<<<dim3(4, 1), 256>>>(pCH, pCL, 1024, pWinH, pWinL, bin_, pP,
                                      512, 2048, 1, 0);
    // ---- gather + pack X ----
    gather_pack_kernel<<<(cTB * 512 + 255) / 256, 256>>>(tok64, tok32, emb);

    // ---- precompute A0u/A0r/A0c = X @ Wx + b ----
    dim3 gpre(4, cTB / 128);
    big_gemm_pre<<<gpre, 256>>>(pXH, pXL, 512, pWu0xH, pWu0xL, bu0, pA0u, 512, 1024, 0, 0);
    big_gemm_pre<<<gpre, 256>>>(pXH, pXL, 512, pWr0xH, pWr0xL, br0, pA0r, 512, 1024, 0, 0);
    big_gemm_pre<<<gpre, 256>>>(pXH, pXL, 512, pWc0xH, pWc0xL, bc0, pA0c, 512, 1024, 0, 0);

    // ---- persistent recurrent loop (all 25 steps, one launch) ----
    loop_kernel<<<128, 256>>>(bu1, br1, bc1);

    // ---- logits = H1 @ Wout + bout -> [B,T,V] ----
    big_gemm_pre<<<dim3((cV + 127) / 128, cTB / 128), 256>>>(
        pH1H, pH1L, 256, pWoutH, pWoutL, bout, out, cV, 512, 0, 1);

    hidden_out_kernel<<<(cB * cH + 255) / 256, 256>>>(out);
}

// round 9
// speedup vs baseline: 1.3769x; 1.1335x over previous
#include <cuda_runtime.h>
#include <cuda_bf16.h>
#include <math.h>
#include <stdint.h>

// ---------------------------------------------------------------------------
// ImageCaptionModel GRU decoder. B=128,T=25,V=10000,E=512,NF=2048,H=512.
// Round 9 (base = passing round 7, 1641 us):
//  - tcgen05 unavailable (ptxas targets compute_103; all tcgen05 rejected) ->
//    mma.sync HMMA path retained everywhere.
//  - 13 prep launches fused into 1 (prep_kernel); launch order arranged so
//    ncu (-s 5, +2 harness launches) profiles pre3_gemm (the GEMM engine).
//  - input layer: split-K (32 blocks, atomicAdd partials), bias+leaky folded
//    into gather.
//  - gemm_core: double-buffered smem, ONE __syncthreads per k16 iteration.
//  - loop_kernel byte-identical to round 7.
// Math: 3-pass bf16-split mma.m16n8k16 (AhiBhi+AhiBlo+AloBhi, fp32 acc).
// ---------------------------------------------------------------------------

namespace {
constexpr int cB = 128, cT = 25, cV = 10000, cE = 512;
constexpr int cH = 512, cMAP = 512, cTB = cB * cT;
constexpr long long LOGITS_ELEMS = (long long)cB * cT * cV;
}

// -------- scratch (__device__ globals; no allocation allowed) --------------
__device__ float d_P[cB * cMAP];
__device__ uint32_t d_CH[cB * 1024], d_CL[cB * 1024];          // cnn packed [m][kp]
__device__ uint32_t d_XH[cTB * 512], d_XL[cTB * 512];          // X packed [m][kp]
__device__ float d_A0u[cTB * cH], d_A0r[cTB * cH], d_A0c[cTB * cH];
__device__ uint32_t d_H1H[cTB * 256], d_H1L[cTB * 256];
__device__ float d_h0f[cB * cH], d_h1f[cB * cH];
__device__ float d_U0[cB * cH], d_U1[cB * cH];
__device__ uint32_t d_h0pH[cB * 256], d_h0pL[cB * 256];
__device__ uint32_t d_h1pH[cB * 256], d_h1pL[cB * 256];
__device__ uint32_t d_RH0H[cB * 256], d_RH0L[cB * 256];
__device__ uint32_t d_RH1H[cB * 256], d_RH1L[cB * 256];
// k-major packed weights [kp][N]
__device__ uint32_t d_WinH[1024 * 512], d_WinL[1024 * 512];
__device__ uint32_t d_Wu0xH[512 * 512], d_Wu0xL[512 * 512];
__device__ uint32_t d_Wr0xH[512 * 512], d_Wr0xL[512 * 512];
__device__ uint32_t d_Wc0xH[512 * 512], d_Wc0xL[512 * 512];
__device__ uint32_t d_WoutH[256 * 10000], d_WoutL[256 * 10000];
// n-major packed weights [n][kp]
__device__ uint32_t d_WU0hH[512 * 256], d_WU0hL[512 * 256];
__device__ uint32_t d_WR0hH[512 * 256], d_WR0hL[512 * 256];
__device__ uint32_t d_WC0rhH[512 * 256], d_WC0rhL[512 * 256];
__device__ uint32_t d_WU1H[512 * 512], d_WU1L[512 * 512];
__device__ uint32_t d_WR1H[512 * 512], d_WR1L[512 * 512];
__device__ uint32_t d_WC1H[512 * 512], d_WC1L[512 * 512];
__device__ int d_tok64;
__device__ unsigned g_cnt = 0;
__device__ volatile unsigned g_gen = 0;

// -------- helpers ----------------------------------------------------------
__device__ __forceinline__ float sigf(float x) { return 1.0f / (1.0f + __expf(-x)); }

__device__ __forceinline__ void bf16_split(float a, float b, uint32_t& hi, uint32_t& lo) {
    __nv_bfloat162 h;
    h.x = __float2bfloat16_rn(a);
    h.y = __float2bfloat16_rn(b);
    __nv_bfloat162 l;
    l.x = __float2bfloat16_rn(a - __bfloat162float(h.x));
    l.y = __float2bfloat16_rn(b - __bfloat162float(h.y));
    hi = *reinterpret_cast<uint32_t*>(&h);
    lo = *reinterpret_cast<uint32_t*>(&l);
}

__device__ __forceinline__ void mma_bf(
    float& c0, float& c1, float& c2, float& c3,
    uint32_t a0, uint32_t a1, uint32_t a2, uint32_t a3,
    uint32_t b0, uint32_t b1)
{
    asm volatile(
        "mma.sync.aligned.m16n8k16.row.col.f32.bf16.bf16.f32 "
        "{%0,%1,%2,%3}, {%4,%5,%6,%7}, {%8,%9}, {%0,%1,%2,%3};\n"
        : "+f"(c0), "+f"(c1), "+f"(c2), "+f"(c3)
        : "r"(a0), "r"(a1), "r"(a2), "r"(a3), "r"(b0), "r"(b1));
}

// ---------------------------------------------------------------------------
// prep_kernel: block 0 = token dtype detect; blocks 1.. = flat work list:
//   init(65536) | cnnA(131072) | Win(524288) | W*0x(3x262144) |
//   Wout(2560000) | W*h n-major K2=256 (3x131072) | W*1 n-major (3x262144)
// ---------------------------------------------------------------------------
__global__ void prep_kernel(const long long* __restrict__ t64,
    const float* __restrict__ cnn, const float* __restrict__ Win,
    const float* __restrict__ Wout,
    const float* __restrict__ Wu0, const float* __restrict__ Wr0,
    const float* __restrict__ Wc0,
    const float* __restrict__ Wu1, const float* __restrict__ Wr1,
    const float* __restrict__ Wc1)
{
    const int tid = threadIdx.x;
    if (blockIdx.x == 0) {
        __shared__ int bad;
        if (tid == 0) bad = 0;
        __syncthreads();
        for (int i = tid; i < cTB / 2; i += 256) {
            long long v = t64[i];
            if (v < 0 || v >= (long long)cV) bad = 1;
        }
        __syncthreads();
        if (tid == 0) d_tok64 = (bad == 0) ? 1 : 0;
        return;
    }
    long long idx = (long long)(blockIdx.x - 1) * 256 + tid;
    if (idx < 65536) {
        int i = (int)idx;
        d_h0f[i] = 0.f; d_h1f[i] = 0.f; d_P[i] = 0.f;
        if (i < 32768) {
            d_h0pH[i] = 0u; d_h0pL[i] = 0u;
            d_h1pH[i] = 0u; d_h1pL[i] = 0u;
        }
        return;
    }
    idx -= 65536;
    if (idx < 131072) {                     // cnn A pack [m][kp], K2=1024
        int m = (int)(idx >> 10), kp = (int)(idx & 1023);
        float2 v = *(const float2*)(cnn + (long long)m * 2048 + 2 * kp);
        uint32_t h, l; bf16_split(v.x, v.y, h, l);
        d_CH[idx] = h; d_CL[idx] = l;
        return;
    }
    idx -= 131072;
    if (idx < 524288) {                     // Win k-major [1024][512]
        int kp = (int)(idx >> 9), n = (int)(idx & 511);
        uint32_t h, l;
        bf16_split(Win[(long long)(2 * kp) * 512 + n], Win[(long long)(2 * kp + 1) * 512 + n], h, l);
        d_WinH[idx] = h; d_WinL[idx] = l;
        return;
    }
    idx -= 524288;
    if (idx < 786432) {                     // Wu0x/Wr0x/Wc0x k-major [512][512]
        int w = (int)(idx >> 18);
        long long r = idx & 262143;
        const float* s = (w == 0) ? Wu0 : ((w == 1) ? Wr0 : (Wc0 + 512 * 512));
        uint32_t* oh = (w == 0) ? d_Wu0xH : ((w == 1) ? d_Wr0xH : d_Wc0xH);
        uint32_t* ol = (w == 0) ? d_Wu0xL : ((w == 1) ? d_Wr0xL : d_Wc0xL);
        int kp = (int)(r >> 9), n = (int)(r & 511);
        uint32_t h, l;
        bf16_split(s[(2 * kp) * 512 + n], s[(2 * kp + 1) * 512 + n], h, l);
        oh[r] = h; ol[r] = l;
        return;
    }
    idx -= 786432;
    if (idx < 2560000) {                    // Wout k-major [256][10000]
        int kp = (int)(idx / 10000);
        int n = (int)(idx - (long long)kp * 10000);
        uint32_t h, l;
        bf16_split(Wout[(long long)(2 * kp) * 10000 + n],
                   Wout[(long long)(2 * kp + 1) * 10000 + n], h, l);
        d_WoutH[idx] = h; d_WoutL[idx] = l;
        return;
    }
    idx -= 2560000;
    if (idx < 393216) {                     // WU0h/WR0h/WC0rh n-major [512][256]
        int w = (int)(idx >> 17);
        long long r = idx & 131071;
        const float* s = (w == 0) ? (Wu0 + 1024 * 512) : ((w == 1) ? (Wr0 + 1024 * 512) : Wc0);
        uint32_t* oh = (w == 0) ? d_WU0hH : ((w == 1) ? d_WR0hH : d_WC0rhH);
        uint32_t* ol = (w == 0) ? d_WU0hL : ((w == 1) ? d_WR0hL : d_WC0rhL);
        int n = (int)(r >> 8), kp = (int)(r & 255);
        uint32_t h, l;
        bf16_split(s[(2 * kp) * 512 + n], s[(2 * kp + 1) * 512 + n], h, l);
        oh[r] = h; ol[r] = l;
        return;
    }
    idx -= 393216;
    if (idx < 786432) {                     // WU1/WR1/WC1 n-major [512][512]
        int w = (int)(idx >> 18);
        long long r = idx & 262143;
        const float* s = (w == 0) ? Wu1 : ((w == 1) ? Wr1 : Wc1);
        uint32_t* oh = (w == 0) ? d_WU1H : ((w == 1) ? d_WR1H : d_WC1H);
        uint32_t* ol = (w == 0) ? d_WU1L : ((w == 1) ? d_WR1L : d_WC1L);
        int n = (int)(r >> 9), kp = (int)(r & 511);
        uint32_t h, l;
        bf16_split(s[(2 * kp) * 512 + n], s[(2 * kp + 1) * 512 + n], h, l);
        oh[r] = h; ol[r] = l;
    }
}

// X packed: row m=t*B+b, kp<256 -> emb pair, else leaky(P_sum + bin) pair
__global__ void gather_pack_kernel(const long long* __restrict__ tok64,
                                   const int* __restrict__ tok32,
                                   const float* __restrict__ emb,
                                   const float* __restrict__ bin_) {
    int idx = blockIdx.x * blockDim.x + threadIdx.x;
    if (idx >= cTB * 512) return;
    int m = idx >> 9, kp = idx & 511;
    int tt = m / cB, b = m % cB;
    float2 v;
    if (kp < 256) {
        int tok = d_tok64 ? (int)tok64[b * cT + tt] : tok32[b * cT + tt];
        v = *(const float2*)(emb + (long long)tok * cE + 2 * kp);
    } else {
        int k2 = kp - 256;
        float2 raw = *(const float2*)(d_P + b * cMAP + 2 * k2);
        v.x = raw.x + bin_[2 * k2];
        v.y = raw.y + bin_[2 * k2 + 1];
        v.x = v.x > 0.f ? v.x : 0.01f * v.x;
        v.y = v.y > 0.f ? v.y : 0.01f * v.y;
    }
    uint32_t h, l;
    bf16_split(v.x, v.y, h, l);
    d_XH[idx] = h; d_XL[idx] = l;
}

// ---------------------------------------------------------------------------
// gemm_core: C[128 x 128 tile] = unpack(A)@unpack(B) (+bias)(+act), 3-pass.
// A packed [M][as]; B packed k-major [K/2][N]. Double-buffered smem,
// ONE __syncthreads per k16 iteration. atomic=1 -> atomicAdd partials.
// ---------------------------------------------------------------------------
__device__ __forceinline__ void gemm_core(
    const uint32_t* __restrict__ AH, const uint32_t* __restrict__ AL, int as,
    const uint32_t* __restrict__ BH, const uint32_t* __restrict__ BL,
    const float* __restrict__ bias, float* __restrict__ C,
    int N, int K, int act, int remap, int atomic, int m0, int n0)
{
    __shared__ uint32_t AsH[2][128][8], AsL[2][128][8];
    __shared__ uint32_t BsH[2][128][9], BsL[2][128][9];
    const int tid = threadIdx.x;
    const int wid = tid >> 5, lane = tid & 31;
    const int grp = lane >> 2, tig = lane & 3;
    const int wm = (wid >> 1) * 32, wn = (wid & 1) * 64;
    const int ar = tid >> 2, kb = (tid & 3) << 1;
    const int kp = (tid >> 4) & 7;
    const int bn = ((tid & 15) << 2) + ((tid >> 7) << 6);
    const int NC = K >> 4;

    float acc[2][8][4] = {};
    uint2 a0h, a0l, a1h, a1l;
    uint4 bh, bl;

    // prefetch chunk 0 + store buf 0
    {
        const uint32_t* pa = AH + (long long)(m0 + ar) * as + kb;
        const uint32_t* pl = AL + (long long)(m0 + ar) * as + kb;
        a0h = *(const uint2*)pa; a1h = *(const uint2*)(pa + (long long)64 * as);
        a0l = *(const uint2*)pl; a1l = *(const uint2*)(pl + (long long)64 * as);
        int n = n0 + bn;
        if (n < N) {
            bh = *(const uint4*)(BH + (long long)kp * N + n);
            bl = *(const uint4*)(BL + (long long)kp * N + n);
        } else { bh = make_uint4(0, 0, 0, 0); bl = bh; }
    }
    AsH[0][ar][kb] = a0h.x; AsH[0][ar][kb + 1] = a0h.y;
    AsH[0][ar + 64][kb] = a1h.x; AsH[0][ar + 64][kb + 1] = a1h.y;
    AsL[0][ar][kb] = a0l.x; AsL[0][ar][kb + 1] = a0l.y;
    AsL[0][ar + 64][kb] = a1l.x; AsL[0][ar + 64][kb + 1] = a1l.y;
    BsH[0][bn + 0][kp] = bh.x; BsH[0][bn + 1][kp] = bh.y;
    BsH[0][bn + 2][kp] = bh.z; BsH[0][bn + 3][kp] = bh.w;
    BsL[0][bn + 0][kp] = bl.x; BsL[0][bn + 1][kp] = bl.y;
    BsL[0][bn + 2][kp] = bl.z; BsL[0][bn + 3][kp] = bl.w;
    __syncthreads();

    for (int c = 0; c < NC; c++) {
        const int buf = c & 1;
        const int kn = (c + 1) << 4;
        if (kn < K) {   // prefetch next chunk into regs
            const uint32_t* pa = AH + (long long)(m0 + ar) * as + (kn >> 1) + kb;
            const uint32_t* pl = AL + (long long)(m0 + ar) * as + (kn >> 1) + kb;
            a0h = *(const uint2*)pa; a1h = *(const uint2*)(pa + (long long)64 * as);
            a0l = *(const uint2*)pl; a1l = *(const uint2*)(pl + (long long)64 * as);
            int n = n0 + bn;
            if (n < N) {
                bh = *(const uint4*)(BH + (long long)((kn >> 1) + kp) * N + n);
                bl = *(const uint4*)(BL + (long long)((kn >> 1) + kp) * N + n);
            } else { bh = make_uint4(0, 0, 0, 0); bl = bh; }
        }

        // compute on buf
        uint32_t aHf[2][4], aLf[2][4];
#pragma unroll
        for (int mf = 0; mf < 2; mf++) {
            int mb = wm + mf * 16;
            aHf[mf][0] = AsH[buf][mb + grp][tig];         aLf[mf][0] = AsL[buf][mb + grp][tig];
            aHf[mf][1] = AsH[buf][mb + 8 + grp][tig];     aLf[mf][1] = AsL[buf][mb + 8 + grp][tig];
            aHf[mf][2] = AsH[buf][mb + grp][tig + 4];     aLf[mf][2] = AsL[buf][mb + grp][tig + 4];
            aHf[mf][3] = AsH[buf][mb + 8 + grp][tig + 4]; aLf[mf][3] = AsL[buf][mb + 8 + grp][tig + 4];
        }
#pragma unroll
        for (int nf = 0; nf < 8; nf++) {
            int nb = wn + nf * 8 + grp;
            uint32_t b0H = BsH[buf][nb][tig], b1H = BsH[buf][nb][tig + 4];
            uint32_t b0L = BsL[buf][nb][tig], b1L = BsL[buf][nb][tig + 4];
#pragma unroll
            for (int mf = 0; mf < 2; mf++) {
                float* cc = acc[mf][nf];
                mma_bf(cc[0], cc[1], cc[2], cc[3],
                       aHf[mf][0], aHf[mf][1], aHf[mf][2], aHf[mf][3], b0H, b1H);
                mma_bf(cc[0], cc[1], cc[2], cc[3],
                       aHf[mf][0], aHf[mf][1], aHf[mf][2], aHf[mf][3], b0L, b1L);
                mma_bf(cc[0], cc[1], cc[2], cc[3],
                       aLf[mf][0], aLf[mf][1], aLf[mf][2], aLf[mf][3], b0H, b1H);
            }
        }

        // store prefetched regs into the other buffer (WAR-safe: different buf)
        if (kn < K) {
            const int nb2 = buf ^ 1;
            AsH[nb2][ar][kb] = a0h.x; AsH[nb2][ar][kb + 1] = a0h.y;
            AsH[nb2][ar + 64][kb] = a1h.x; AsH[nb2][ar + 64][kb + 1] = a1h.y;
            AsL[nb2][ar][kb] = a0l.x; AsL[nb2][ar][kb + 1] = a0l.y;
            AsL[nb2][ar + 64][kb] = a1l.x; AsL[nb2][ar + 64][kb + 1] = a1l.y;
            BsH[nb2][bn + 0][kp] = bh.x; BsH[nb2][bn + 1][kp] = bh.y;
            BsH[nb2][bn + 2][kp] = bh.z; BsH[nb2][bn + 3][kp] = bh.w;
            BsL[nb2][bn + 0][kp] = bl.x; BsL[nb2][bn + 1][kp] = bl.y;
            BsL[nb2][bn + 2][kp] = bl.z; BsL[nb2][bn + 3][kp] = bl.w;
        }
        __syncthreads();
    }

    // epilogue
#pragma unroll
    for (int mf = 0; mf < 2; mf++) {
        int r0 = m0 + wm + mf * 16 + grp;
        int r1 = r0 + 8;
        long long base0, base1;
        if (remap) {
            int b0r = r0 & (cB - 1), t0 = r0 >> 7;
            int b1r = r1 & (cB - 1), t1 = r1 >> 7;
            base0 = (long long)(b0r * cT + t0) * N;
            base1 = (long long)(b1r * cT + t1) * N;
        } else {
            base0 = (long long)r0 * N;
            base1 = (long long)r1 * N;
        }
#pragma unroll
        for (int nf = 0; nf < 8; nf++) {
            int n = n0 + wn + nf * 8 + tig * 2;
            if (n < N) {
                if (atomic) {
                    atomicAdd(C + base0 + n,     acc[mf][nf][0]);
                    atomicAdd(C + base0 + n + 1, acc[mf][nf][1]);
                    atomicAdd(C + base1 + n,     acc[mf][nf][2]);
                    atomicAdd(C + base1 + n + 1, acc[mf][nf][3]);
                } else {
                    float o00 = acc[mf][nf][0] + bias[n];
                    float o01 = acc[mf][nf][1] + bias[n + 1];
                    float o10 = acc[mf][nf][2] + bias[n];
                    float o11 = acc[mf][nf][3] + bias[n + 1];
                    if (act == 1) {
                        o00 = o00 > 0.f ? o00 : 0.01f * o00;
                        o01 = o01 > 0.f ? o01 : 0.01f * o01;
                        o10 = o10 > 0.f ? o10 : 0.01f * o10;
                        o11 = o11 > 0.f ? o11 : 0.01f * o11;
                    }
                    C[base0 + n] = o00; C[base0 + n + 1] = o01;
                    C[base1 + n] = o10; C[base1 + n + 1] = o11;
                }
            }
        }
    }
}

// wrappers -------------------------------------------------------------------
__global__ __launch_bounds__(256) void input_gemm() {
    // grid (4 n-tiles, 8 k-chunks); partials atomically summed into d_P
    int chunk = blockIdx.y;
    gemm_core(d_CH + chunk * 128, d_CL + chunk * 128, 1024,
              d_WinH + chunk * 65536, d_WinL + chunk * 65536,
              nullptr, d_P, 512, 256, 0, 0, 1, 0, blockIdx.x * 128);
}

__global__ __launch_bounds__(256) void pre3_gemm(
    const float* __restrict__ bu0, const float* __restrict__ br0,
    const float* __restrict__ bc0) {
    int z = blockIdx.z;
    const uint32_t* BH = (z == 0) ? d_Wu0xH : ((z == 1) ? d_Wr0xH : d_Wc0xH);
    const uint32_t* BL = (z == 0) ? d_Wu0xL : ((z == 1) ? d_Wr0xL : d_Wc0xL);
    const float* bias = (z == 0) ? bu0 : ((z == 1) ? br0 : bc0);
    float* C = (z == 0) ? d_A0u : ((z == 1) ? d_A0r : d_A0c);
    gemm_core(d_XH, d_XL, 512, BH, BL, bias, C, 512, 1024, 0, 0, 0,
              blockIdx.y * 128, blockIdx.x * 128);
}

__global__ __launch_bounds__(256) void logits_gemm(
    const float* __restrict__ bout, float* __restrict__ out) {
    gemm_core(d_H1H, d_H1L, 256, d_WoutH, d_WoutL, bout, out, cV, 512, 0, 1, 0,
              blockIdx.y * 128, blockIdx.x * 128);
}

// ---------------------------------------------------------------------------
// Persistent recurrent kernel (byte-identical to round 7 — passing).
// ---------------------------------------------------------------------------
__device__ __forceinline__ void grid_bar() {
    __syncthreads();
    if (threadIdx.x == 0) {
        unsigned gen = g_gen;
        __threadfence();
        if (atomicAdd(&g_cnt, 1u) == 127u) {
            atomicExch(&g_cnt, 0u);
            __threadfence();
            g_gen = gen + 1;
        } else {
            while (g_gen == gen) { }
        }
        __threadfence();
    }
    __syncthreads();
}

template <int NITER, int MF>
__device__ __forceinline__ void tile_gemm(
    const uint32_t* __restrict__ AH, const uint32_t* __restrict__ AL, int kpa0,
    const uint32_t* __restrict__ BH, const uint32_t* __restrict__ BL, int bs, int kpb0,
    int m0, int n0, int grp, int tig, float (&acc)[MF][4][4])
{
#pragma unroll
    for (int it = 0; it < NITER; it++) {
        const int kpA = kpa0 + it * 8, kpB = kpb0 + it * 8;
        uint32_t aH[MF][4], aL[MF][4];
#pragma unroll
        for (int mf = 0; mf < MF; mf++) {
            const int r = (m0 + mf * 16 + grp) * 256 + kpA;
            aH[mf][0] = __ldcg(AH + r + tig);        aH[mf][1] = __ldcg(AH + r + 2048 + tig);
            aH[mf][2] = __ldcg(AH + r + tig + 4);    aH[mf][3] = __ldcg(AH + r + 2048 + tig + 4);
            aL[mf][0] = __ldcg(AL + r + tig);        aL[mf][1] = __ldcg(AL + r + 2048 + tig);
            aL[mf][2] = __ldcg(AL + r + tig + 4);    aL[mf][3] = __ldcg(AL + r + 2048 + tig + 4);
        }
#pragma unroll
        for (int nf = 0; nf < 4; nf++) {
            const int nb = (n0 + nf * 8 + grp) * bs + kpB;
            uint32_t b0H = __ldg(BH + nb + tig), b1H = __ldg(BH + nb + tig + 4);
            uint32_t b0L = __ldg(BL + nb + tig), b1L = __ldg(BL + nb + tig + 4);
#pragma unroll
            for (int mf = 0; mf < MF; mf++) {
                float* c = acc[mf][nf];
                mma_bf(c[0], c[1], c[2], c[3],
                       aH[mf][0], aH[mf][1], aH[mf][2], aH[mf][3], b0H, b1H);
                mma_bf(c[0], c[1], c[2], c[3],
                       aH[mf][0], aH[mf][1], aH[mf][2], aH[mf][3], b0L, b1L);
                mma_bf(c[0], c[1], c[2], c[3],
                       aL[mf][0], aL[mf][1], aL[mf][2], aL[mf][3], b0H, b1H);
            }
        }
    }
}

template <int MF>
__device__ __forceinline__ void store_red(float (*red)[1024], float (&acc)[MF][4][4],
                                          int wid, int grp, int tig) {
#pragma unroll
    for (int mf = 0; mf < MF; mf++)
#pragma unroll
        for (int nf = 0; nf < 4; nf++) {
            int c = nf * 8 + tig * 2, r = mf * 16 + grp;
            red[wid][r * 32 + c] = acc[mf][nf][0];
            red[wid][r * 32 + c + 1] = acc[mf][nf][1];
            red[wid][(r + 8) * 32 + c] = acc[mf][nf][2];
            red[wid][(r + 8) * 32 + c + 1] = acc[mf][nf][3];
        }
}

__device__ __forceinline__ float4 sum_red4(float (*red)[1024], int e0) {
    float4 s = make_float4(0, 0, 0, 0);
#pragma unroll
    for (int w = 0; w < 8; w++) {
        float4 r = *(float4*)&red[w][e0];
        s.x += r.x; s.y += r.y; s.z += r.z; s.w += r.w;
    }
    return s;
}

__device__ __forceinline__ float2 sum_red2(float (*red)[1024], int e0) {
    float2 s = make_float2(0, 0);
#pragma unroll
    for (int w = 0; w < 8; w++) {
        float2 r = *(float2*)&red[w][e0];
        s.x += r.x; s.y += r.y;
    }
    return s;
}

__global__ __launch_bounds__(256) void loop_kernel(
    const float* __restrict__ bu1, const float* __restrict__ br1,
    const float* __restrict__ bc1)
{
    __shared__ float red[8][1024];
    const int tid = threadIdx.x, wid = tid >> 5, lane = tid & 31;
    const int grp = lane >> 2, tig = lane & 3;
    const int blk = blockIdx.x;

    for (int t = 0; t < cT; t++) {
        // ---- phase A: u0 (blk<64) / r0 (blk>=64), 32x32 tiles, K=512 ----
        {
            int gate = blk >> 6, tile = blk & 63;
            int m0 = (tile & 3) * 32, n0 = (tile >> 2) * 32;
            float acc[2][4][4] = {};
            tile_gemm<4, 2>(d_h0pH, d_h0pL, wid * 32,
                            gate ? d_WR0hH : d_WU0hH, gate ? d_WR0hL : d_WU0hL,
                            256, wid * 32, m0, n0, grp, tig, acc);
            store_red<2>(red, acc, wid, grp, tig);
            __syncthreads();
            const float* A0 = (gate ? d_A0r : d_A0u) + t * cB * cH;
            int e0 = tid * 4;
            float4 s = sum_red4(red, e0);
            int m = m0 + (e0 >> 5), n = n0 + (e0 & 31), o = m * cH + n;
            float4 a = *(const float4*)(A0 + o);
            if (gate == 0) {
                d_U0[o] = sigf(a.x + s.x);     d_U0[o + 1] = sigf(a.y + s.y);
                d_U0[o + 2] = sigf(a.z + s.z); d_U0[o + 3] = sigf(a.w + s.w);
            } else {
                float r0 = sigf(a.x + s.x) * __ldcg(d_h0f + o);
                float r1 = sigf(a.y + s.y) * __ldcg(d_h0f + o + 1);
                float r2 = sigf(a.z + s.z) * __ldcg(d_h0f + o + 2);
                float r3 = sigf(a.w + s.w) * __ldcg(d_h0f + o + 3);
                uint32_t h, l;
                int kp = m * 256 + (n >> 1);
                bf16_split(r0, r1, h, l); d_RH0H[kp] = h;     d_RH0L[kp] = l;
                bf16_split(r2, r3, h, l); d_RH0H[kp + 1] = h; d_RH0L[kp + 1] = l;
            }
        }
        grid_bar();
        // ---- phase B: c0, 16x32 tiles, K=512, in-place h0 update ----
        {
            int m0 = (blk & 7) * 16, n0 = (blk >> 3) * 32;
            float acc[1][4][4] = {};
            tile_gemm<4, 1>(d_RH0H, d_RH0L, wid * 32,
                            d_WC0rhH, d_WC0rhL, 256, wid * 32, m0, n0, grp, tig, acc);
            store_red<1>(red, acc, wid, grp, tig);
            __syncthreads();
            const float* A0 = d_A0c + t * cB * cH;
            int e0 = tid * 2;
            float2 s = sum_red2(red, e0);
            int m = m0 + (e0 >> 5), n = n0 + (e0 & 31), o = m * cH + n;
            float v0 = A0[o] + s.x, v1 = A0[o + 1] + s.y;
            float u0 = __ldcg(d_U0 + o), u1 = __ldcg(d_U0 + o + 1);
            float p0 = __ldcg(d_h0f + o), p1 = __ldcg(d_h0f + o + 1);
            float n0v = u0 * p0 + (1.f - u0) * tanhf(v0);
            float n1v = u1 * p1 + (1.f - u1) * tanhf(v1);
            d_h0f[o] = n0v; d_h0f[o + 1] = n1v;
            uint32_t h, l;
            bf16_split(n0v, n1v, h, l);
            int kp = m * 256 + (n >> 1);
            d_h0pH[kp] = h; d_h0pL[kp] = l;
        }
        grid_bar();
        // ---- phase C: u1 / r1, 32x32 tiles, K=1024 ([h0,h1]) ----
        {
            int gate = blk >> 6, tile = blk & 63;
            int m0 = (tile & 3) * 32, n0 = (tile >> 2) * 32;
            float acc[2][4][4] = {};
            tile_gemm<8, 2>((wid < 4) ? d_h0pH : d_h1pH, (wid < 4) ? d_h0pL : d_h1pL,
                            (wid & 3) * 64,
                            gate ? d_WR1H : d_WU1H, gate ? d_WR1L : d_WU1L,
                            512, wid * 64, m0, n0, grp, tig, acc);
            store_red<2>(red, acc, wid, grp, tig);
            __syncthreads();
            const float* bb = gate ? br1 : bu1;
            int e0 = tid * 4;
            float4 s = sum_red4(red, e0);
            int m = m0 + (e0 >> 5), n = n0 + (e0 & 31), o = m * cH + n;
            float4 b = *(const float4*)(bb + n);
            if (gate == 0) {
                d_U1[o] = sigf(b.x + s.x);     d_U1[o + 1] = sigf(b.y + s.y);
                d_U1[o + 2] = sigf(b.z + s.z); d_U1[o + 3] = sigf(b.w + s.w);
            } else {
                float r0 = sigf(b.x + s.x) * __ldcg(d_h1f + o);
                float r1 = sigf(b.y + s.y) * __ldcg(d_h1f + o + 1);
                float r2 = sigf(b.z + s.z) * __ldcg(d_h1f + o + 2);
                float r3 = sigf(b.w + s.w) * __ldcg(d_h1f + o + 3);
                uint32_t h, l;
                int kp = m * 256 + (n >> 1);
                bf16_split(r0, r1, h, l); d_RH1H[kp] = h;     d_RH1L[kp] = l;
                bf16_split(r2, r3, h, l); d_RH1H[kp + 1] = h; d_RH1L[kp + 1] = l;
            }
        }
        grid_bar();
        // ---- phase D: c1, 16x32 tiles, K=1024 ([RH1,h0]); no barrier after ----
        {
            int m0 = (blk & 7) * 16, n0 = (blk >> 3) * 32;
            float acc[1][4][4] = {};
            tile_gemm<8, 1>((wid < 4) ? d_RH1H : d_h0pH, (wid < 4) ? d_RH1L : d_h0pL,
                            (wid & 3) * 64,
                            d_WC1H, d_WC1L, 512, wid * 64, m0, n0, grp, tig, acc);
            store_red<1>(red, acc, wid, grp, tig);
            __syncthreads();
            int e0 = tid * 2;
            float2 s = sum_red2(red, e0);
            int m = m0 + (e0 >> 5), n = n0 + (e0 & 31), o = m * cH + n;
            float v0 = bc1[n] + s.x, v1 = bc1[n + 1] + s.y;
            float u0 = __ldcg(d_U1 + o), u1 = __ldcg(d_U1 + o + 1);
            float p0 = __ldcg(d_h1f + o), p1 = __ldcg(d_h1f + o + 1);
            float n0v = u0 * p0 + (1.f - u0) * tanhf(v0);
            float n1v = u1 * p1 + (1.f - u1) * tanhf(v1);
            d_h1f[o] = n0v; d_h1f[o + 1] = n1v;
            uint32_t h, l;
            bf16_split(n0v, n1v, h, l);
            int kp = m * 256 + (n >> 1);
            d_h1pH[kp] = h; d_h1pL[kp] = l;
            long long hp = (long long)(t * cB + m) * 256 + (n >> 1);
            d_H1H[hp] = h; d_H1L[hp] = l;
            __syncthreads();
        }
    }
}

__global__ void hidden_out_kernel(float* __restrict__ out) {
    int i = blockIdx.x * blockDim.x + threadIdx.x;
    if (i < cB * cH) {
        out[LOGITS_ELEMS + i] = d_h0f[i];
        out[LOGITS_ELEMS + cB * cH + i] = d_h1f[i];
    }
}

// ---------------------------------------------------------------------------
extern "C" void kernel_launch(void* const* d_in, const int* in_sizes, int n_in,
                              void* d_out, int out_size) {
    const long long* tok64 = (const long long*)d_in[0];
    const int*       tok32 = (const int*)d_in[0];
    const float* cnn  = (const float*)d_in[1];
    const float* emb  = (const float*)d_in[2];
    const float* Win  = (const float*)d_in[3];
    const float* bin_ = (const float*)d_in[4];
    const float* Wout = (const float*)d_in[5];
    const float* bout = (const float*)d_in[6];
    const float* Wu0  = (const float*)d_in[7];
    const float* bu0  = (const float*)d_in[8];
    const float* Wr0  = (const float*)d_in[9];
    const float* br0  = (const float*)d_in[10];
    const float* Wc0  = (const float*)d_in[11];
    const float* bc0  = (const float*)d_in[12];
    const float* Wu1  = (const float*)d_in[13];
    const float* bu1  = (const float*)d_in[14];
    const float* Wr1  = (const float*)d_in[15];
    const float* br1  = (const float*)d_in[16];
    const float* Wc1  = (const float*)d_in[17];
    const float* bc1  = (const float*)d_in[18];
    float* out = (float*)d_out;

    // launch 0: fused prep (detect + init + all packing); 5246976 work items
    prep_kernel<<<20497, 256>>>(tok64, cnn, Win, Wout, Wu0, Wr0, Wc0, Wu1, Wr1, Wc1);
    // launch 1: input layer split-K partial sums into d_P
    input_gemm<<<dim3(4, 8), 256>>>();
    // launch 2: gather + bias/leaky on P + pack X
    gather_pack_kernel<<<(cTB * 512 + 255) / 256, 256>>>(tok64, tok32, emb, bin_);
    // launch 3 (ncu-profiled): fused precompute A0u/A0r/A0c = X @ Wx + b
    pre3_gemm<<<dim3(4, 25, 3), 256>>>(bu0, br0, bc0);
    // launch 4: persistent recurrent loop (all 25 steps)
    loop_kernel<<<128, 256>>>(bu1, br1, bc1);
    // launch 5: logits = H1 @ Wout + bout -> [B,T,V]
    logits_gemm<<<dim3((cV + 127) / 128, 25), 256>>>(bout, out);
    // launch 6: hidden state outputs
    hidden_out_kernel<<<(cB * cH + 255) / 256, 256>>>(out);
}

// round 13
// speedup vs baseline: 1.4178x; 1.0297x over previous
#include <cuda_runtime.h>
#include <cuda_bf16.h>
#include <math.h>
#include <stdint.h>

// ---------------------------------------------------------------------------
// ImageCaptionModel GRU decoder. B=128,T=25,V=10000,E=512,NF=2048,H=512.
// Round 12R (resubmission; broker timeouts rounds 10-12):
//  - GEMM engine: ldmatrix.x4 fragment loads from xor-swizzled smem
//    (conflict-free; replaces 48 conflicted LDS.32/warp/iter with 12 LDSM).
//  - pre3 tiles fused into loop_kernel head (balanced over 128 persistent
//    blocks; shared pool aliases the 32KB reduction buffer) -> fused kernel
//    is launch #3 and gets ncu-profiled next round.
// Math: 3-pass bf16-split mma.m16n8k16 (AhiBhi+AhiBlo+AloBhi, fp32 acc).
// ---------------------------------------------------------------------------

namespace {
constexpr int cB = 128, cT = 25, cV = 10000, cE = 512;
constexpr int cH = 512, cMAP = 512, cTB = cB * cT;
constexpr long long LOGITS_ELEMS = (long long)cB * cT * cV;
}

// -------- scratch (__device__ globals; no allocation allowed) --------------
__device__ float d_P[cB * cMAP];
__device__ uint32_t d_CH[cB * 1024], d_CL[cB * 1024];
__device__ uint32_t d_XH[cTB * 512], d_XL[cTB * 512];
__device__ float d_A0u[cTB * cH], d_A0r[cTB * cH], d_A0c[cTB * cH];
__device__ uint32_t d_H1H[cTB * 256], d_H1L[cTB * 256];
__device__ float d_h0f[cB * cH], d_h1f[cB * cH];
__device__ float d_U0[cB * cH], d_U1[cB * cH];
__device__ uint32_t d_h0pH[cB * 256], d_h0pL[cB * 256];
__device__ uint32_t d_h1pH[cB * 256], d_h1pL[cB * 256];
__device__ uint32_t d_RH0H[cB * 256], d_RH0L[cB * 256];
__device__ uint32_t d_RH1H[cB * 256], d_RH1L[cB * 256];
// k-major packed weights [kp][N]
__device__ uint32_t d_WinH[1024 * 512], d_WinL[1024 * 512];
__device__ uint32_t d_Wu0xH[512 * 512], d_Wu0xL[512 * 512];
__device__ uint32_t d_Wr0xH[512 * 512], d_Wr0xL[512 * 512];
__device__ uint32_t d_Wc0xH[512 * 512], d_Wc0xL[512 * 512];
__device__ uint32_t d_WoutH[256 * 10000], d_WoutL[256 * 10000];
// n-major packed weights [n][kp]
__device__ uint32_t d_WU0hH[512 * 256], d_WU0hL[512 * 256];
__device__ uint32_t d_WR0hH[512 * 256], d_WR0hL[512 * 256];
__device__ uint32_t d_WC0rhH[512 * 256], d_WC0rhL[512 * 256];
__device__ uint32_t d_WU1H[512 * 512], d_WU1L[512 * 512];
__device__ uint32_t d_WR1H[512 * 512], d_WR1L[512 * 512];
__device__ uint32_t d_WC1H[512 * 512], d_WC1L[512 * 512];
__device__ int d_tok64;
__device__ unsigned g_cnt = 0;
__device__ volatile unsigned g_gen = 0;

// -------- helpers ----------------------------------------------------------
__device__ __forceinline__ float sigf(float x) { return 1.0f / (1.0f + __expf(-x)); }

__device__ __forceinline__ void bf16_split(float a, float b, uint32_t& hi, uint32_t& lo) {
    __nv_bfloat162 h;
    h.x = __float2bfloat16_rn(a);
    h.y = __float2bfloat16_rn(b);
    __nv_bfloat162 l;
    l.x = __float2bfloat16_rn(a - __bfloat162float(h.x));
    l.y = __float2bfloat16_rn(b - __bfloat162float(h.y));
    hi = *reinterpret_cast<uint32_t*>(&h);
    lo = *reinterpret_cast<uint32_t*>(&l);
}

__device__ __forceinline__ void mma_bf(
    float& c0, float& c1, float& c2, float& c3,
    uint32_t a0, uint32_t a1, uint32_t a2, uint32_t a3,
    uint32_t b0, uint32_t b1)
{
    asm volatile(
        "mma.sync.aligned.m16n8k16.row.col.f32.bf16.bf16.f32 "
        "{%0,%1,%2,%3}, {%4,%5,%6,%7}, {%8,%9}, {%0,%1,%2,%3};\n"
        : "+f"(c0), "+f"(c1), "+f"(c2), "+f"(c3)
        : "r"(a0), "r"(a1), "r"(a2), "r"(a3), "r"(b0), "r"(b1));
}

__device__ __forceinline__ void ldsm4(uint32_t& r0, uint32_t& r1, uint32_t& r2,
                                      uint32_t& r3, uint32_t addr) {
    asm volatile("ldmatrix.sync.aligned.m8n8.x4.shared.b16 {%0,%1,%2,%3}, [%4];"
                 : "=r"(r0), "=r"(r1), "=r"(r2), "=r"(r3) : "r"(addr));
}

__device__ __forceinline__ uint32_t smem_u32(const void* p) {
    uint32_t a;
    asm("{ .reg .u64 t; cvta.to.shared.u64 t, %1; cvt.u32.u64 %0, t; }" : "=r"(a) : "l"(p));
    return a;
}

// swizzled byte offset of 16B-unit (row r in [0,128), half h in {0,1}) within
// a 4KB operand array: macro_row = r>>2, unit = ((r&3)*2+h) ^ (macro_row&7).
// Conflict-free for LDSM (any aligned 8-row read hits 8 distinct bank-quads).
__device__ __forceinline__ uint32_t sw_off(int r, int h) {
    return (uint32_t)(((r >> 2) << 7) + (((((r & 3) << 1) + h) ^ ((r >> 2) & 7)) << 4));
}

// -------- prep / gather ----------------------------------------------------
__global__ void prep_kernel(const long long* __restrict__ t64,
    const float* __restrict__ cnn, const float* __restrict__ Win,
    const float* __restrict__ Wout,
    const float* __restrict__ Wu0, const float* __restrict__ Wr0,
    const float* __restrict__ Wc0,
    const float* __restrict__ Wu1, const float* __restrict__ Wr1,
    const float* __restrict__ Wc1)
{
    const int tid = threadIdx.x;
    if (blockIdx.x == 0) {
        __shared__ int bad;
        if (tid == 0) bad = 0;
        __syncthreads();
        for (int i = tid; i < cTB / 2; i += 256) {
            long long v = t64[i];
            if (v < 0 || v >= (long long)cV) bad = 1;
        }
        __syncthreads();
        if (tid == 0) d_tok64 = (bad == 0) ? 1 : 0;
        return;
    }
    long long idx = (long long)(blockIdx.x - 1) * 256 + tid;
    if (idx < 65536) {
        int i = (int)idx;
        d_h0f[i] = 0.f; d_h1f[i] = 0.f; d_P[i] = 0.f;
        if (i < 32768) {
            d_h0pH[i] = 0u; d_h0pL[i] = 0u;
            d_h1pH[i] = 0u; d_h1pL[i] = 0u;
        }
        return;
    }
    idx -= 65536;
    if (idx < 131072) {
        int m = (int)(idx >> 10), kp = (int)(idx & 1023);
        float2 v = *(const float2*)(cnn + (long long)m * 2048 + 2 * kp);
        uint32_t h, l; bf16_split(v.x, v.y, h, l);
        d_CH[idx] = h; d_CL[idx] = l;
        return;
    }
    idx -= 131072;
    if (idx < 524288) {
        int kp = (int)(idx >> 9), n = (int)(idx & 511);
        uint32_t h, l;
        bf16_split(Win[(long long)(2 * kp) * 512 + n], Win[(long long)(2 * kp + 1) * 512 + n], h, l);
        d_WinH[idx] = h; d_WinL[idx] = l;
        return;
    }
    idx -= 524288;
    if (idx < 786432) {
        int w = (int)(idx >> 18);
        long long r = idx & 262143;
        const float* s = (w == 0) ? Wu0 : ((w == 1) ? Wr0 : (Wc0 + 512 * 512));
        uint32_t* oh = (w == 0) ? d_Wu0xH : ((w == 1) ? d_Wr0xH : d_Wc0xH);
        uint32_t* ol = (w == 0) ? d_Wu0xL : ((w == 1) ? d_Wr0xL : d_Wc0xL);
        int kp = (int)(r >> 9), n = (int)(r & 511);
        uint32_t h, l;
        bf16_split(s[(2 * kp) * 512 + n], s[(2 * kp + 1) * 512 + n], h, l);
        oh[r] = h; ol[r] = l;
        return;
    }
    idx -= 786432;
    if (idx < 2560000) {
        int kp = (int)(idx / 10000);
        int n = (int)(idx - (long long)kp * 10000);
        uint32_t h, l;
        bf16_split(Wout[(long long)(2 * kp) * 10000 + n],
                   Wout[(long long)(2 * kp + 1) * 10000 + n], h, l);
        d_WoutH[idx] = h; d_WoutL[idx] = l;
        return;
    }
    idx -= 2560000;
    if (idx < 393216) {
        int w = (int)(idx >> 17);
        long long r = idx & 131071;
        const float* s = (w == 0) ? (Wu0 + 1024 * 512) : ((w == 1) ? (Wr0 + 1024 * 512) : Wc0);
        uint32_t* oh = (w == 0) ? d_WU0hH : ((w == 1) ? d_WR0hH : d_WC0rhH);
        uint32_t* ol = (w == 0) ? d_WU0hL : ((w == 1) ? d_WR0hL : d_WC0rhL);
        int n = (int)(r >> 8), kp = (int)(r & 255);
        uint32_t h, l;
        bf16_split(s[(2 * kp) * 512 + n], s[(2 * kp + 1) * 512 + n], h, l);
        oh[r] = h; ol[r] = l;
        return;
    }
    idx -= 393216;
    if (idx < 786432) {
        int w = (int)(idx >> 18);
        long long r = idx & 262143;
        const float* s = (w == 0) ? Wu1 : ((w == 1) ? Wr1 : Wc1);
        uint32_t* oh = (w == 0) ? d_WU1H : ((w == 1) ? d_WR1H : d_WC1H);
        uint32_t* ol = (w == 0) ? d_WU1L : ((w == 1) ? d_WR1L : d_WC1L);
        int n = (int)(r >> 9), kp = (int)(r & 511);
        uint32_t h, l;
        bf16_split(s[(2 * kp) * 512 + n], s[(2 * kp + 1) * 512 + n], h, l);
        oh[r] = h; ol[r] = l;
    }
}

__global__ void gather_pack_kernel(const long long* __restrict__ tok64,
                                   const int* __restrict__ tok32,
                                   const float* __restrict__ emb,
                                   const float* __restrict__ bin_) {
    int idx = blockIdx.x * blockDim.x + threadIdx.x;
    if (idx >= cTB * 512) return;
    int m = idx >> 9, kp = idx & 511;
    int tt = m / cB, b = m % cB;
    float2 v;
    if (kp < 256) {
        int tok = d_tok64 ? (int)tok64[b * cT + tt] : tok32[b * cT + tt];
        v = *(const float2*)(emb + (long long)tok * cE + 2 * kp);
    } else {
        int k2 = kp - 256;
        float2 raw = *(const float2*)(d_P + b * cMAP + 2 * k2);
        v.x = raw.x + bin_[2 * k2];
        v.y = raw.y + bin_[2 * k2 + 1];
        v.x = v.x > 0.f ? v.x : 0.01f * v.x;
        v.y = v.y > 0.f ? v.y : 0.01f * v.y;
    }
    uint32_t h, l;
    bf16_split(v.x, v.y, h, l);
    d_XH[idx] = h; d_XL[idx] = l;
}

// ---------------------------------------------------------------------------
// gemm_core (ldmatrix edition). Pool layout per buffer (16KB):
//   [0,4K) A-hi  [4K,8K) A-lo  [8K,12K) B-hi  [12K,16K) B-lo
// Each operand: 128 rows x 32B, xor-swizzled (sw_off). Double buffered: 32KB.
// ---------------------------------------------------------------------------
__device__ __forceinline__ void gemm_core(
    const uint32_t* __restrict__ AH, const uint32_t* __restrict__ AL, int as,
    const uint32_t* __restrict__ BH, const uint32_t* __restrict__ BL,
    const float* __restrict__ bias, float* __restrict__ C,
    int N, int K, int act, int remap, int atomic, int m0, int n0, char* pool)
{
    const uint32_t sbase = smem_u32(pool);
    const int tid = threadIdx.x;
    const int wid = tid >> 5, lane = tid & 31;
    const int grp = lane >> 2, tig = lane & 3;
    const int wm = (wid >> 1) * 32, wn = (wid & 1) * 64;
    const int ar = tid >> 2, kb = (tid & 3) << 1;
    const int kp = (tid >> 4) & 7;
    const int bn = ((tid & 15) << 2) + ((tid >> 7) << 6);
    const int NC = K >> 4;

    const uint32_t oA0 = sw_off(ar, kb >> 2) + ((kb & 3) << 2);
    const uint32_t oA1 = sw_off(ar + 64, kb >> 2) + ((kb & 3) << 2);
    uint32_t oB[4];
#pragma unroll
    for (int j = 0; j < 4; j++) oB[j] = sw_off(bn + j, kp >> 2) + ((kp & 3) << 2);

    const int rA = (lane & 15);
    const uint32_t hA = (uint32_t)(lane >> 4);
    const int rB = (lane & 7) + ((lane >> 4) << 3);
    const uint32_t hB = (uint32_t)((lane >> 3) & 1);

    float acc[2][8][4] = {};
    uint2 a0h, a0l, a1h, a1l;
    uint4 bh, bl;

    {
        const uint32_t* pa = AH + (long long)(m0 + ar) * as + kb;
        const uint32_t* pl = AL + (long long)(m0 + ar) * as + kb;
        a0h = *(const uint2*)pa; a1h = *(const uint2*)(pa + (long long)64 * as);
        a0l = *(const uint2*)pl; a1l = *(const uint2*)(pl + (long long)64 * as);
        int n = n0 + bn;
        if (n < N) {
            bh = *(const uint4*)(BH + (long long)kp * N + n);
            bl = *(const uint4*)(BL + (long long)kp * N + n);
        } else { bh = make_uint4(0, 0, 0, 0); bl = bh; }
    }
    {
        char* pA = pool;
        char* pB = pool + 8192;
        *(uint2*)(pA + oA0) = a0h; *(uint2*)(pA + oA1) = a1h;
        *(uint2*)(pA + 4096 + oA0) = a0l; *(uint2*)(pA + 4096 + oA1) = a1l;
        *(uint32_t*)(pB + oB[0]) = bh.x; *(uint32_t*)(pB + oB[1]) = bh.y;
        *(uint32_t*)(pB + oB[2]) = bh.z; *(uint32_t*)(pB + oB[3]) = bh.w;
        *(uint32_t*)(pB + 4096 + oB[0]) = bl.x; *(uint32_t*)(pB + 4096 + oB[1]) = bl.y;
        *(uint32_t*)(pB + 4096 + oB[2]) = bl.z; *(uint32_t*)(pB + 4096 + oB[3]) = bl.w;
    }
    __syncthreads();

    for (int c = 0; c < NC; c++) {
        const int buf = c & 1;
        const int kn = (c + 1) << 4;
        if (kn < K) {
            const uint32_t* pa = AH + (long long)(m0 + ar) * as + (kn >> 1) + kb;
            const uint32_t* pl = AL + (long long)(m0 + ar) * as + (kn >> 1) + kb;
            a0h = *(const uint2*)pa; a1h = *(const uint2*)(pa + (long long)64 * as);
            a0l = *(const uint2*)pl; a1l = *(const uint2*)(pl + (long long)64 * as);
            int n = n0 + bn;
            if (n < N) {
                bh = *(const uint4*)(BH + (long long)((kn >> 1) + kp) * N + n);
                bl = *(const uint4*)(BL + (long long)((kn >> 1) + kp) * N + n);
            } else { bh = make_uint4(0, 0, 0, 0); bl = bh; }
        }

        const uint32_t base = sbase + (uint32_t)buf * 16384;
        uint32_t aHf[2][4], aLf[2][4];
#pragma unroll
        for (int mf = 0; mf < 2; mf++) {
            uint32_t addr = base + sw_off(wm + mf * 16 + rA, hA);
            ldsm4(aHf[mf][0], aHf[mf][1], aHf[mf][2], aHf[mf][3], addr);
            ldsm4(aLf[mf][0], aLf[mf][1], aLf[mf][2], aLf[mf][3], addr + 4096);
        }
#pragma unroll
        for (int nfp = 0; nfp < 4; nfp++) {
            uint32_t addrB = base + 8192 + sw_off(wn + nfp * 16 + rB, hB);
            uint32_t bH0, bH1, bH2, bH3, bL0, bL1, bL2, bL3;
            ldsm4(bH0, bH1, bH2, bH3, addrB);
            ldsm4(bL0, bL1, bL2, bL3, addrB + 4096);
#pragma unroll
            for (int mf = 0; mf < 2; mf++) {
                float* c0 = acc[mf][nfp * 2];
                float* c1 = acc[mf][nfp * 2 + 1];
                mma_bf(c0[0], c0[1], c0[2], c0[3],
                       aHf[mf][0], aHf[mf][1], aHf[mf][2], aHf[mf][3], bH0, bH1);
                mma_bf(c0[0], c0[1], c0[2], c0[3],
                       aHf[mf][0], aHf[mf][1], aHf[mf][2], aHf[mf][3], bL0, bL1);
                mma_bf(c0[0], c0[1], c0[2], c0[3],
                       aLf[mf][0], aLf[mf][1], aLf[mf][2], aLf[mf][3], bH0, bH1);
                mma_bf(c1[0], c1[1], c1[2], c1[3],
                       aHf[mf][0], aHf[mf][1], aHf[mf][2], aHf[mf][3], bH2, bH3);
                mma_bf(c1[0], c1[1], c1[2], c1[3],
                       aHf[mf][0], aHf[mf][1], aHf[mf][2], aHf[mf][3], bL2, bL3);
                mma_bf(c1[0], c1[1], c1[2], c1[3],
                       aLf[mf][0], aLf[mf][1], aLf[mf][2], aLf[mf][3], bH2, bH3);
            }
        }

        if (kn < K) {
            char* pA = pool + (buf ^ 1) * 16384;
            char* pB = pA + 8192;
            *(uint2*)(pA + oA0) = a0h; *(uint2*)(pA + oA1) = a1h;
            *(uint2*)(pA + 4096 + oA0) = a0l; *(uint2*)(pA + 4096 + oA1) = a1l;
            *(uint32_t*)(pB + oB[0]) = bh.x; *(uint32_t*)(pB + oB[1]) = bh.y;
            *(uint32_t*)(pB + oB[2]) = bh.z; *(uint32_t*)(pB + oB[3]) = bh.w;
            *(uint32_t*)(pB + 4096 + oB[0]) = bl.x; *(uint32_t*)(pB + 4096 + oB[1]) = bl.y;
            *(uint32_t*)(pB + 4096 + oB[2]) = bl.z; *(uint32_t*)(pB + 4096 + oB[3]) = bl.w;
        }
        __syncthreads();
    }

#pragma unroll
    for (int mf = 0; mf < 2; mf++) {
        int r0 = m0 + wm + mf * 16 + grp;
        int r1 = r0 + 8;
        long long base0, base1;
        if (remap) {
            int b0r = r0 & (cB - 1), t0 = r0 >> 7;
            int b1r = r1 & (cB - 1), t1 = r1 >> 7;
            base0 = (long long)(b0r * cT + t0) * N;
            base1 = (long long)(b1r * cT + t1) * N;
        } else {
            base0 = (long long)r0 * N;
            base1 = (long long)r1 * N;
        }
#pragma unroll
        for (int nf = 0; nf < 8; nf++) {
            int n = n0 + wn + nf * 8 + tig * 2;
            if (n < N) {
                if (atomic) {
                    atomicAdd(C + base0 + n,     acc[mf][nf][0]);
                    atomicAdd(C + base0 + n + 1, acc[mf][nf][1]);
                    atomicAdd(C + base1 + n,     acc[mf][nf][2]);
                    atomicAdd(C + base1 + n + 1, acc[mf][nf][3]);
                } else {
                    float o00 = acc[mf][nf][0] + bias[n];
                    float o01 = acc[mf][nf][1] + bias[n + 1];
                    float o10 = acc[mf][nf][2] + bias[n];
                    float o11 = acc[mf][nf][3] + bias[n + 1];
                    if (act == 1) {
                        o00 = o00 > 0.f ? o00 : 0.01f * o00;
                        o01 = o01 > 0.f ? o01 : 0.01f * o01;
                        o10 = o10 > 0.f ? o10 : 0.01f * o10;
                        o11 = o11 > 0.f ? o11 : 0.01f * o11;
                    }
                    C[base0 + n] = o00; C[base0 + n + 1] = o01;
                    C[base1 + n] = o10; C[base1 + n + 1] = o11;
                }
            }
        }
    }
}

// wrappers -------------------------------------------------------------------
__global__ __launch_bounds__(256) void input_gemm() {
    __shared__ __align__(16) char pool[32768];
    int chunk = blockIdx.y;
    gemm_core(d_CH + chunk * 128, d_CL + chunk * 128, 1024,
              d_WinH + chunk * 65536, d_WinL + chunk * 65536,
              nullptr, d_P, 512, 256, 0, 0, 1, 0, blockIdx.x * 128, pool);
}

__global__ __launch_bounds__(256) void logits_gemm(
    const float* __restrict__ bout, float* __restrict__ out) {
    __shared__ __align__(16) char pool[32768];
    gemm_core(d_H1H, d_H1L, 256, d_WoutH, d_WoutL, bout, out, cV, 512, 0, 1, 0,
              blockIdx.y * 128, blockIdx.x * 128, pool);
}

// ---------------------------------------------------------------------------
// Persistent kernel: pre-phase (300 precompute tiles over 128 blocks) +
// 25-step recurrent loop (phases identical to round 7/9 passing code).
// ---------------------------------------------------------------------------
__device__ __forceinline__ void grid_bar() {
    __syncthreads();
    if (threadIdx.x == 0) {
        unsigned gen = g_gen;
        __threadfence();
        if (atomicAdd(&g_cnt, 1u) == 127u) {
            atomicExch(&g_cnt, 0u);
            __threadfence();
            g_gen = gen + 1;
        } else {
            while (g_gen == gen) { }
        }
        __threadfence();
    }
    __syncthreads();
}

template <int NITER, int MF>
__device__ __forceinline__ void tile_gemm(
    const uint32_t* __restrict__ AH, const uint32_t* __restrict__ AL, int kpa0,
    const uint32_t* __restrict__ BH, const uint32_t* __restrict__ BL, int bs, int kpb0,
    int m0, int n0, int grp, int tig, float (&acc)[MF][4][4])
{
#pragma unroll
    for (int it = 0; it < NITER; it++) {
        const int kpA = kpa0 + it * 8, kpB = kpb0 + it * 8;
        uint32_t aH[MF][4], aL[MF][4];
#pragma unroll
        for (int mf = 0; mf < MF; mf++) {
            const int r = (m0 + mf * 16 + grp) * 256 + kpA;
            aH[mf][0] = __ldcg(AH + r + tig);        aH[mf][1] = __ldcg(AH + r + 2048 + tig);
            aH[mf][2] = __ldcg(AH + r + tig + 4);    aH[mf][3] = __ldcg(AH + r + 2048 + tig + 4);
            aL[mf][0] = __ldcg(AL + r + tig);        aL[mf][1] = __ldcg(AL + r + 2048 + tig);
            aL[mf][2] = __ldcg(AL + r + tig + 4);    aL[mf][3] = __ldcg(AL + r + 2048 + tig + 4);
        }
#pragma unroll
        for (int nf = 0; nf < 4; nf++) {
            const int nb = (n0 + nf * 8 + grp) * bs + kpB;
            uint32_t b0H = __ldg(BH + nb + tig), b1H = __ldg(BH + nb + tig + 4);
            uint32_t b0L = __ldg(BL + nb + tig), b1L = __ldg(BL + nb + tig + 4);
#pragma unroll
            for (int mf = 0; mf < MF; mf++) {
                float* c = acc[mf][nf];
                mma_bf(c[0], c[1], c[2], c[3],
                       aH[mf][0], aH[mf][1], aH[mf][2], aH[mf][3], b0H, b1H);
                mma_bf(c[0], c[1], c[2], c[3],
                       aH[mf][0], aH[mf][1], aH[mf][2], aH[mf][3], b0L, b1L);
                mma_bf(c[0], c[1], c[2], c[3],
                       aL[mf][0], aL[mf][1], aL[mf][2], aL[mf][3], b0H, b1H);
            }
        }
    }
}

template <int MF>
__device__ __forceinline__ void store_red(float (*red)[1024], float (&acc)[MF][4][4],
                                          int wid, int grp, int tig) {
#pragma unroll
    for (int mf = 0; mf < MF; mf++)
#pragma unroll
        for (int nf = 0; nf < 4; nf++) {
            int c = nf * 8 + tig * 2, r = mf * 16 + grp;
            red[wid][r * 32 + c] = acc[mf][nf][0];
            red[wid][r * 32 + c + 1] = acc[mf][nf][1];
            red[wid][(r + 8) * 32 + c] = acc[mf][nf][2];
            red[wid][(r + 8) * 32 + c + 1] = acc[mf][nf][3];
        }
}

__device__ __forceinline__ float4 sum_red4(float (*red)[1024], int e0) {
    float4 s = make_float4(0, 0, 0, 0);
#pragma unroll
    for (int w = 0; w < 8; w++) {
        float4 r = *(float4*)&red[w][e0];
        s.x += r.x; s.y += r.y; s.z += r.z; s.w += r.w;
    }
    return s;
}

__device__ __forceinline__ float2 sum_red2(float (*red)[1024], int e0) {
    float2 s = make_float2(0, 0);
#pragma unroll
    for (int w = 0; w < 8; w++) {
        float2 r = *(float2*)&red[w][e0];
        s.x += r.x; s.y += r.y;
    }
    return s;
}

__global__ __launch_bounds__(256) void loop_kernel(
    const float* __restrict__ bu0, const float* __restrict__ br0,
    const float* __restrict__ bc0,
    const float* __restrict__ bu1, const float* __restrict__ br1,
    const float* __restrict__ bc1)
{
    __shared__ __align__(16) char pool[32768];
    const int tid = threadIdx.x, wid = tid >> 5, lane = tid & 31;
    const int grp = lane >> 2, tig = lane & 3;
    const int blk = blockIdx.x;

    // ---- pre-phase: A0u/A0r/A0c = X @ Wx + b  (300 tiles over 128 blocks) ----
    for (int tile = blk; tile < 300; tile += 128) {
        int z = tile / 100, rem = tile - z * 100;
        int my = rem >> 2, nx = rem & 3;
        const uint32_t* BH = (z == 0) ? d_Wu0xH : ((z == 1) ? d_Wr0xH : d_Wc0xH);
        const uint32_t* BL = (z == 0) ? d_Wu0xL : ((z == 1) ? d_Wr0xL : d_Wc0xL);
        const float* bias = (z == 0) ? bu0 : ((z == 1) ? br0 : bc0);
        float* C = (z == 0) ? d_A0u : ((z == 1) ? d_A0r : d_A0c);
        gemm_core(d_XH, d_XL, 512, BH, BL, bias, C, 512, 1024, 0, 0, 0,
                  my * 128, nx * 128, pool);
        __syncthreads();
    }
    grid_bar();

    float (*red)[1024] = (float(*)[1024])pool;

    for (int t = 0; t < cT; t++) {
        // ---- phase A: u0 (blk<64) / r0 (blk>=64), 32x32 tiles, K=512 ----
        {
            int gate = blk >> 6, tile = blk & 63;
            int m0 = (tile & 3) * 32, n0 = (tile >> 2) * 32;
            float acc[2][4][4] = {};
            tile_gemm<4, 2>(d_h0pH, d_h0pL, wid * 32,
                            gate ? d_WR0hH : d_WU0hH, gate ? d_WR0hL : d_WU0hL,
                            256, wid * 32, m0, n0, grp, tig, acc);
            store_red<2>(red, acc, wid, grp, tig);
            __syncthreads();
            const float* A0 = (gate ? d_A0r : d_A0u) + t * cB * cH;
            int e0 = tid * 4;
            float4 s = sum_red4(red, e0);
            int m = m0 + (e0 >> 5), n = n0 + (e0 & 31), o = m * cH + n;
            float4 a = *(const float4*)(A0 + o);
            if (gate == 0) {
                d_U0[o] = sigf(a.x + s.x);     d_U0[o + 1] = sigf(a.y + s.y);
                d_U0[o + 2] = sigf(a.z + s.z); d_U0[o + 3] = sigf(a.w + s.w);
            } else {
                float r0 = sigf(a.x + s.x) * __ldcg(d_h0f + o);
                float r1 = sigf(a.y + s.y) * __ldcg(d_h0f + o + 1);
                float r2 = sigf(a.z + s.z) * __ldcg(d_h0f + o + 2);
                float r3 = sigf(a.w + s.w) * __ldcg(d_h0f + o + 3);
                uint32_t h, l;
                int kp = m * 256 + (n >> 1);
                bf16_split(r0, r1, h, l); d_RH0H[kp] = h;     d_RH0L[kp] = l;
                bf16_split(r2, r3, h, l); d_RH0H[kp + 1] = h; d_RH0L[kp + 1] = l;
            }
        }
        grid_bar();
        // ---- phase B: c0, 16x32 tiles, K=512, in-place h0 update ----
        {
            int m0 = (blk & 7) * 16, n0 = (blk >> 3) * 32;
            float acc[1][4][4] = {};
            tile_gemm<4, 1>(d_RH0H, d_RH0L, wid * 32,
                            d_WC0rhH, d_WC0rhL, 256, wid * 32, m0, n0, grp, tig, acc);
            store_red<1>(red, acc, wid, grp, tig);
            __syncthreads();
            const float* A0 = d_A0c + t * cB * cH;
            int e0 = tid * 2;
            float2 s = sum_red2(red, e0);
            int m = m0 + (e0 >> 5), n = n0 + (e0 & 31), o = m * cH + n;
            float v0 = A0[o] + s.x, v1 = A0[o + 1] + s.y;
            float u0 = __ldcg(d_U0 + o), u1 = __ldcg(d_U0 + o + 1);
            float p0 = __ldcg(d_h0f + o), p1 = __ldcg(d_h0f + o + 1);
            float n0v = u0 * p0 + (1.f - u0) * tanhf(v0);
            float n1v = u1 * p1 + (1.f - u1) * tanhf(v1);
            d_h0f[o] = n0v; d_h0f[o + 1] = n1v;
            uint32_t h, l;
            bf16_split(n0v, n1v, h, l);
            int kp = m * 256 + (n >> 1);
            d_h0pH[kp] = h; d_h0pL[kp] = l;
        }
        grid_bar();
        // ---- phase C: u1 / r1, 32x32 tiles, K=1024 ([h0,h1]) ----
        {
            int gate = blk >> 6, tile = blk & 63;
            int m0 = (tile & 3) * 32, n0 = (tile >> 2) * 32;
            float acc[2][4][4] = {};
            tile_gemm<8, 2>((wid < 4) ? d_h0pH : d_h1pH, (wid < 4) ? d_h0pL : d_h1pL,
                            (wid & 3) * 64,
                            gate ? d_WR1H : d_WU1H, gate ? d_WR1L : d_WU1L,
                            512, wid * 64, m0, n0, grp, tig, acc);
            store_red<2>(red, acc, wid, grp, tig);
            __syncthreads();
            const float* bb = gate ? br1 : bu1;
            int e0 = tid * 4;
            float4 s = sum_red4(red, e0);
            int m = m0 + (e0 >> 5), n = n0 + (e0 & 31), o = m * cH + n;
            float4 b = *(const float4*)(bb + n);
            if (gate == 0) {
                d_U1[o] = sigf(b.x + s.x);     d_U1[o + 1] = sigf(b.y + s.y);
                d_U1[o + 2] = sigf(b.z + s.z); d_U1[o + 3] = sigf(b.w + s.w);
            } else {
                float r0 = sigf(b.x + s.x) * __ldcg(d_h1f + o);
                float r1 = sigf(b.y + s.y) * __ldcg(d_h1f + o + 1);
                float r2 = sigf(b.z + s.z) * __ldcg(d_h1f + o + 2);
                float r3 = sigf(b.w + s.w) * __ldcg(d_h1f + o + 3);
                uint32_t h, l;
                int kp = m * 256 + (n >> 1);
                bf16_split(r0, r1, h, l); d_RH1H[kp] = h;     d_RH1L[kp] = l;
                bf16_split(r2, r3, h, l); d_RH1H[kp + 1] = h; d_RH1L[kp + 1] = l;
            }
        }
        grid_bar();
        // ---- phase D: c1, 16x32 tiles, K=1024 ([RH1,h0]); no barrier after ----
        {
            int m0 = (blk & 7) * 16, n0 = (blk >> 3) * 32;
            float acc[1][4][4] = {};
            tile_gemm<8, 1>((wid < 4) ? d_RH1H : d_h0pH, (wid < 4) ? d_RH1L : d_h0pL,
                            (wid & 3) * 64,
                            d_WC1H, d_WC1L, 512, wid * 64, m0, n0, grp, tig, acc);
            store_red<1>(red, acc, wid, grp, tig);
            __syncthreads();
            int e0 = tid * 2;
            float2 s = sum_red2(red, e0);
            int m = m0 + (e0 >> 5), n = n0 + (e0 & 31), o = m * cH + n;
            float v0 = bc1[n] + s.x, v1 = bc1[n + 1] + s.y;
            float u0 = __ldcg(d_U1 + o), u1 = __ldcg(d_U1 + o + 1);
            float p0 = __ldcg(d_h1f + o), p1 = __ldcg(d_h1f + o + 1);
            float n0v = u0 * p0 + (1.f - u0) * tanhf(v0);
            float n1v = u1 * p1 + (1.f - u1) * tanhf(v1);
            d_h1f[o] = n0v; d_h1f[o + 1] = n1v;
            uint32_t h, l;
            bf16_split(n0v, n1v, h, l);
            int kp = m * 256 + (n >> 1);
            d_h1pH[kp] = h; d_h1pL[kp] = l;
            long long hp = (long long)(t * cB + m) * 256 + (n >> 1);
            d_H1H[hp] = h; d_H1L[hp] = l;
            __syncthreads();
        }
    }
}

__global__ void hidden_out_kernel(float* __restrict__ out) {
    int i = blockIdx.x * blockDim.x + threadIdx.x;
    if (i < cB * cH) {
        out[LOGITS_ELEMS + i] = d_h0f[i];
        out[LOGITS_ELEMS + cB * cH + i] = d_h1f[i];
    }
}

// ---------------------------------------------------------------------------
extern "C" void kernel_launch(void* const* d_in, const int* in_sizes, int n_in,
                              void* d_out, int out_size) {
    const long long* tok64 = (const long long*)d_in[0];
    const int*       tok32 = (const int*)d_in[0];
    const float* cnn  = (const float*)d_in[1];
    const float* emb  = (const float*)d_in[2];
    const float* Win  = (const float*)d_in[3];
    const float* bin_ = (const float*)d_in[4];
    const float* Wout = (const float*)d_in[5];
    const float* bout = (const float*)d_in[6];
    const float* Wu0  = (const float*)d_in[7];
    const float* bu0  = (const float*)d_in[8];
    const float* Wr0  = (const float*)d_in[9];
    const float* br0  = (const float*)d_in[10];
    const float* Wc0  = (const float*)d_in[11];
    const float* bc0  = (const float*)d_in[12];
    const float* Wu1  = (const float*)d_in[13];
    const float* bu1  = (const float*)d_in[14];
    const float* Wr1  = (const float*)d_in[15];
    const float* br1  = (const float*)d_in[16];
    const float* Wc1  = (const float*)d_in[17];
    const float* bc1  = (const float*)d_in[18];
    float* out = (float*)d_out;

    // launch 0: fused prep (detect + init + all packing)
    prep_kernel<<<20497, 256>>>(tok64, cnn, Win, Wout, Wu0, Wr0, Wc0, Wu1, Wr1, Wc1);
    // launch 1: input layer split-K partial sums into d_P
    input_gemm<<<dim3(4, 8), 256>>>();
    // launch 2: gather + bias/leaky on P + pack X
    gather_pack_kernel<<<(cTB * 512 + 255) / 256, 256>>>(tok64, tok32, emb, bin_);
    // launch 3 (ncu-profiled): precompute tiles + persistent recurrent loop
    loop_kernel<<<128, 256>>>(bu0, br0, bc0, bu1, br1, bc1);
    // launch 4: logits = H1 @ Wout + bout -> [B,T,V]
    logits_gemm<<<dim3((cV + 127) / 128, 25), 256>>>(bout, out);
    // launch 5: hidden state outputs
    hidden_out_kernel<<<(cB * cH + 255) / 256, 256>>>(out);
}